// round 1
// baseline (speedup 1.0000x reference)
#include <cuda_runtime.h>
#include <cuda_bf16.h>

// ---------------------------------------------------------------------------
// GAT 2-layer forward, GB300 (sm_103a)
// Pipeline:
//   CSR build (deg -> scan -> scatter)           [tiny]
//   GEMM1: h1 = x @ W1            [10000,256]x[256,1024]
//   score1: s_src/s_dst per (node, head)
//   agg1:  per-dst softmax + weighted gather-accumulate, +b1, ELU -> act1
//   GEMM2: h2 = act1 @ W2         [10000,1024]x[1024,128]
//   score2
//   agg2 -> d_out (+b2)
// No atomics in any hot loop; h1 (40MB) is L2-resident for the gather.
// ---------------------------------------------------------------------------

#define N_NODES 10000
#define F_IN    256
#define H1      8
#define C1      128
#define HC1     1024     // H1*C1
#define C2      128
#define E_BASE  160000
#define E_TOT   (E_BASE + N_NODES)
#define SLOPE   0.2f

// ---- device scratch (static globals; no allocation at runtime) ----
__device__ float g_h1[N_NODES * HC1];     // x @ W1
__device__ float g_act1[N_NODES * HC1];   // elu(agg1 + b1)
__device__ float g_h2[N_NODES * C2];      // act1 @ W2
__device__ float g_s1s[N_NODES * H1];
__device__ float g_s1d[N_NODES * H1];
__device__ float g_s2s[N_NODES];
__device__ float g_s2d[N_NODES];
__device__ int   g_deg[N_NODES];
__device__ int   g_rows[N_NODES + 1];
__device__ int   g_cur[N_NODES];
__device__ int   g_csr[E_TOT + 16];

// ---------------------------------------------------------------------------
// CSR build
// ---------------------------------------------------------------------------
__global__ void k_zero_deg() {
    int i = blockIdx.x * blockDim.x + threadIdx.x;
    if (i < N_NODES) g_deg[i] = 0;
}

__global__ void k_count(const int* __restrict__ ei, int E) {
    int i = blockIdx.x * blockDim.x + threadIdx.x;
    int tot = E + N_NODES;
    if (i >= tot) return;
    int dst = (i < E) ? ei[E + i] : (i - E);
    atomicAdd(&g_deg[dst], 1);
}

__global__ void k_scan() {
    __shared__ int ssum[1024];
    int tid = threadIdx.x;
    const int CH = (N_NODES + 1023) >> 10;   // 10
    int base = tid * CH;
    int s = 0;
    for (int i = 0; i < CH; i++) {
        int idx = base + i;
        if (idx < N_NODES) s += g_deg[idx];
    }
    ssum[tid] = s;
    __syncthreads();
    // Hillis-Steele inclusive scan
    for (int off = 1; off < 1024; off <<= 1) {
        int v = (tid >= off) ? ssum[tid - off] : 0;
        __syncthreads();
        ssum[tid] += v;
        __syncthreads();
    }
    int run = (tid == 0) ? 0 : ssum[tid - 1];
    for (int i = 0; i < CH; i++) {
        int idx = base + i;
        if (idx < N_NODES) {
            g_rows[idx] = run;
            g_cur[idx]  = run;
            run += g_deg[idx];
        }
    }
    if (tid == 1023) g_rows[N_NODES] = ssum[1023];
}

__global__ void k_scatter(const int* __restrict__ ei, int E) {
    int i = blockIdx.x * blockDim.x + threadIdx.x;
    int tot = E + N_NODES;
    if (i >= tot) return;
    int src = (i < E) ? ei[i]     : (i - E);
    int dst = (i < E) ? ei[E + i] : (i - E);
    int p = atomicAdd(&g_cur[dst], 1);
    g_csr[p] = src;
}

// ---------------------------------------------------------------------------
// SGEMM: C[M,N] = A[M,K] @ B[K,N], row-major, fp32.
// BM=128, BN=64, BK=16, TM=8, TN=4, 256 threads.
// N and K must be multiples of 64/16 (true here: N in {1024,128}, K in {256,1024}).
// ---------------------------------------------------------------------------
template<int BM, int BN, int BK, int TM, int TN>
__global__ __launch_bounds__(256)
void k_sgemm(int M, int N, int K,
             const float* __restrict__ A, const float* __restrict__ B,
             float* __restrict__ C) {
    __shared__ float As[BK][BM + 4];
    __shared__ float Bs[BK][BN];
    const int NT = 256;
    int bm0 = blockIdx.y * BM;
    int bn0 = blockIdx.x * BN;
    int tid = threadIdx.x;
    int tr = tid / (BN / TN);   // 0..15
    int tc = tid % (BN / TN);   // 0..15

    float acc[TM][TN];
#pragma unroll
    for (int i = 0; i < TM; i++)
#pragma unroll
        for (int j = 0; j < TN; j++) acc[i][j] = 0.f;

    for (int k0 = 0; k0 < K; k0 += BK) {
        // Load A tile: BM x BK  (float4 along K)
#pragma unroll
        for (int l = tid; l < BM * BK / 4; l += NT) {
            int row = l / (BK / 4);
            int kq  = (l % (BK / 4)) * 4;
            float4 v = make_float4(0.f, 0.f, 0.f, 0.f);
            int gm = bm0 + row;
            if (gm < M) v = *(const float4*)(A + (size_t)gm * K + k0 + kq);
            As[kq + 0][row] = v.x;
            As[kq + 1][row] = v.y;
            As[kq + 2][row] = v.z;
            As[kq + 3][row] = v.w;
        }
        // Load B tile: BK x BN
#pragma unroll
        for (int l = tid; l < BK * BN / 4; l += NT) {
            int row = l / (BN / 4);
            int nq  = (l % (BN / 4)) * 4;
            *(float4*)&Bs[row][nq] = *(const float4*)(B + (size_t)(k0 + row) * N + bn0 + nq);
        }
        __syncthreads();
#pragma unroll
        for (int k = 0; k < BK; k++) {
            float ra[TM], rb[TN];
#pragma unroll
            for (int i = 0; i < TM; i++) ra[i] = As[k][tr * TM + i];
#pragma unroll
            for (int j = 0; j < TN; j++) rb[j] = Bs[k][tc * TN + j];
#pragma unroll
            for (int i = 0; i < TM; i++)
#pragma unroll
                for (int j = 0; j < TN; j++) acc[i][j] = fmaf(ra[i], rb[j], acc[i][j]);
        }
        __syncthreads();
    }
#pragma unroll
    for (int i = 0; i < TM; i++) {
        int gm = bm0 + tr * TM + i;
        if (gm >= M) continue;
#pragma unroll
        for (int j = 0; j < TN; j += 4) {
            float4 v = make_float4(acc[i][j], acc[i][j + 1], acc[i][j + 2], acc[i][j + 3]);
            *(float4*)(C + (size_t)gm * N + bn0 + tc * TN + j) = v;
        }
    }
}

// ---------------------------------------------------------------------------
// score1: per node, per head h: s = <h1[n,h,:], a[h,:]>   (8 warps = 8 heads)
// ---------------------------------------------------------------------------
__global__ __launch_bounds__(256)
void k_score1(const float* __restrict__ a_src, const float* __restrict__ a_dst) {
    int node = blockIdx.x;
    int wid = threadIdx.x >> 5, lane = threadIdx.x & 31;
    const float* hr  = g_h1 + (size_t)node * HC1 + wid * C1;
    const float* asr = a_src + wid * C1;
    const float* adr = a_dst + wid * C1;
    float s1 = 0.f, s2 = 0.f;
#pragma unroll
    for (int j = 0; j < 4; j++) {
        int c = lane + 32 * j;
        float v = hr[c];
        s1 = fmaf(v, asr[c], s1);
        s2 = fmaf(v, adr[c], s2);
    }
#pragma unroll
    for (int o = 16; o; o >>= 1) {
        s1 += __shfl_xor_sync(~0u, s1, o);
        s2 += __shfl_xor_sync(~0u, s2, o);
    }
    if (!lane) {
        g_s1s[node * H1 + wid] = s1;
        g_s1d[node * H1 + wid] = s2;
    }
}

// ---------------------------------------------------------------------------
// agg1: one block per destination node. 256 threads.
//   pass1: per-head max over incoming edges
//   pass2: per-head softmax denom
//   pass3: chunked alpha precompute (shared) + dense float4 accumulation
//   epilogue: +b1, ELU -> g_act1
// ---------------------------------------------------------------------------
__global__ __launch_bounds__(256)
void k_agg1(const float* __restrict__ b1) {
    int n = blockIdx.x;
    int tid = threadIdx.x, wid = tid >> 5, lane = tid & 31;
    __shared__ float sdl[8], smax[8], sden[8];
    __shared__ float wr[8][8];
    __shared__ float sal[32][8];
    __shared__ int   ssrc[32];

    if (tid < 8) sdl[tid] = g_s1d[n * H1 + tid];
    int r0 = g_rows[n], r1 = g_rows[n + 1];
    int deg = r1 - r0;
    __syncthreads();

    int myh = tid & 7;
    // ---- pass 1: max per head ----
    float mx = -3.0e38f;
    for (int idx = tid; idx < deg * 8; idx += 256) {
        int s = g_csr[r0 + (idx >> 3)];
        float v = g_s1s[s * H1 + myh] + sdl[myh];
        v = v > 0.f ? v : SLOPE * v;
        mx = fmaxf(mx, v);
    }
    mx = fmaxf(mx, __shfl_xor_sync(~0u, mx, 8));
    mx = fmaxf(mx, __shfl_xor_sync(~0u, mx, 16));
    if (lane < 8) wr[wid][lane] = mx;
    __syncthreads();
    if (tid < 8) {
        float m = wr[0][tid];
#pragma unroll
        for (int w = 1; w < 8; w++) m = fmaxf(m, wr[w][tid]);
        smax[tid] = m;
    }
    __syncthreads();

    // ---- pass 2: denom per head ----
    float dn = 0.f;
    for (int idx = tid; idx < deg * 8; idx += 256) {
        int s = g_csr[r0 + (idx >> 3)];
        float v = g_s1s[s * H1 + myh] + sdl[myh];
        v = v > 0.f ? v : SLOPE * v;
        dn += __expf(v - smax[myh]);
    }
    dn += __shfl_xor_sync(~0u, dn, 8);
    dn += __shfl_xor_sync(~0u, dn, 16);
    if (lane < 8) wr[wid][lane] = dn;
    __syncthreads();
    if (tid < 8) {
        float d = 0.f;
#pragma unroll
        for (int w = 0; w < 8; w++) d += wr[w][tid];
        sden[tid] = d;
    }
    __syncthreads();

    // ---- pass 3: accumulate. thread owns channels [tid*4, tid*4+4) -> head = wid ----
    float4 acc = make_float4(0.f, 0.f, 0.f, 0.f);
    int coff = tid * 4;
    for (int e0 = r0; e0 < r1; e0 += 32) {
        int m = min(32, r1 - e0);
        if (tid < m * 8) {
            int e = e0 + (tid >> 3);
            int hh = tid & 7;
            int s = g_csr[e];
            if (hh == 0) ssrc[tid >> 3] = s;
            float v = g_s1s[s * H1 + hh] + sdl[hh];
            v = v > 0.f ? v : SLOPE * v;
            sal[tid >> 3][hh] = __expf(v - smax[hh]) / sden[hh];
        }
        __syncthreads();
        for (int j = 0; j < m; j++) {
            int s = ssrc[j];
            float a = sal[j][wid];
            float4 hv = *(const float4*)(&g_h1[(size_t)s * HC1 + coff]);
            acc.x = fmaf(hv.x, a, acc.x);
            acc.y = fmaf(hv.y, a, acc.y);
            acc.z = fmaf(hv.z, a, acc.z);
            acc.w = fmaf(hv.w, a, acc.w);
        }
        __syncthreads();
    }
    float4 bb = *(const float4*)(&b1[coff]);
    float4 o;
    float t;
    t = acc.x + bb.x; o.x = t > 0.f ? t : expm1f(t);
    t = acc.y + bb.y; o.y = t > 0.f ? t : expm1f(t);
    t = acc.z + bb.z; o.z = t > 0.f ? t : expm1f(t);
    t = acc.w + bb.w; o.w = t > 0.f ? t : expm1f(t);
    *(float4*)(&g_act1[(size_t)n * HC1 + coff]) = o;
}

// ---------------------------------------------------------------------------
// score2: 8 nodes per block (1 warp each), 128 channels, 1 head
// ---------------------------------------------------------------------------
__global__ __launch_bounds__(256)
void k_score2(const float* __restrict__ a_src, const float* __restrict__ a_dst) {
    int node = blockIdx.x * 8 + (threadIdx.x >> 5);
    int lane = threadIdx.x & 31;
    if (node >= N_NODES) return;
    const float* hr = g_h2 + (size_t)node * C2;
    float s1 = 0.f, s2 = 0.f;
#pragma unroll
    for (int j = 0; j < 4; j++) {
        int c = lane + 32 * j;
        float v = hr[c];
        s1 = fmaf(v, a_src[c], s1);
        s2 = fmaf(v, a_dst[c], s2);
    }
#pragma unroll
    for (int o = 16; o; o >>= 1) {
        s1 += __shfl_xor_sync(~0u, s1, o);
        s2 += __shfl_xor_sync(~0u, s2, o);
    }
    if (!lane) {
        g_s2s[node] = s1;
        g_s2d[node] = s2;
    }
}

// ---------------------------------------------------------------------------
// agg2: one block (128 threads) per destination node; writes final output
// ---------------------------------------------------------------------------
__global__ __launch_bounds__(128)
void k_agg2(const float* __restrict__ b2, float* __restrict__ out) {
    int n = blockIdx.x;
    int tid = threadIdx.x, wid = tid >> 5, lane = tid & 31;
    __shared__ float s_sd, s_m, s_d;
    __shared__ float wr[4];
    __shared__ float sal[64];
    __shared__ int   ssrc[64];

    if (tid == 0) s_sd = g_s2d[n];
    int r0 = g_rows[n], r1 = g_rows[n + 1];
    int deg = r1 - r0;
    __syncthreads();
    float sdv = s_sd;

    // pass 1: max
    float mx = -3.0e38f;
    for (int i = tid; i < deg; i += 128) {
        int s = g_csr[r0 + i];
        float v = g_s2s[s] + sdv;
        v = v > 0.f ? v : SLOPE * v;
        mx = fmaxf(mx, v);
    }
#pragma unroll
    for (int o = 16; o; o >>= 1) mx = fmaxf(mx, __shfl_xor_sync(~0u, mx, o));
    if (!lane) wr[wid] = mx;
    __syncthreads();
    if (tid == 0) {
        float m = wr[0];
#pragma unroll
        for (int w = 1; w < 4; w++) m = fmaxf(m, wr[w]);
        s_m = m;
    }
    __syncthreads();
    float m = s_m;

    // pass 2: denom
    float dn = 0.f;
    for (int i = tid; i < deg; i += 128) {
        int s = g_csr[r0 + i];
        float v = g_s2s[s] + sdv;
        v = v > 0.f ? v : SLOPE * v;
        dn += __expf(v - m);
    }
#pragma unroll
    for (int o = 16; o; o >>= 1) dn += __shfl_xor_sync(~0u, dn, o);
    if (!lane) wr[wid] = dn;
    __syncthreads();
    if (tid == 0) s_d = wr[0] + wr[1] + wr[2] + wr[3];
    __syncthreads();
    float den = s_d;

    // pass 3: accumulate channel tid
    float acc = 0.f;
    for (int e0 = r0; e0 < r1; e0 += 64) {
        int mc = min(64, r1 - e0);
        if (tid < mc) {
            int s = g_csr[e0 + tid];
            float v = g_s2s[s] + sdv;
            v = v > 0.f ? v : SLOPE * v;
            sal[tid] = __expf(v - m) / den;
            ssrc[tid] = s;
        }
        __syncthreads();
        for (int j = 0; j < mc; j++)
            acc = fmaf(g_h2[(size_t)ssrc[j] * C2 + tid], sal[j], acc);
        __syncthreads();
    }
    out[(size_t)n * C2 + tid] = acc + b2[tid];
}

// ---------------------------------------------------------------------------
// launch
// ---------------------------------------------------------------------------
extern "C" void kernel_launch(void* const* d_in, const int* in_sizes, int n_in,
                              void* d_out, int out_size) {
    const float* x      = (const float*)d_in[0];
    const int*   ei     = (const int*)  d_in[1];
    const float* W1     = (const float*)d_in[2];
    const float* a_src1 = (const float*)d_in[3];
    const float* a_dst1 = (const float*)d_in[4];
    const float* b1     = (const float*)d_in[5];
    const float* W2     = (const float*)d_in[6];
    const float* a_src2 = (const float*)d_in[7];
    const float* a_dst2 = (const float*)d_in[8];
    const float* b2     = (const float*)d_in[9];
    float* out = (float*)d_out;

    int E = in_sizes[1] / 2;
    int tot = E + N_NODES;

    float *p_h1, *p_act1, *p_h2;
    cudaGetSymbolAddress((void**)&p_h1,   g_h1);
    cudaGetSymbolAddress((void**)&p_act1, g_act1);
    cudaGetSymbolAddress((void**)&p_h2,   g_h2);

    // CSR build
    k_zero_deg<<<(N_NODES + 255) / 256, 256>>>();
    k_count<<<(tot + 255) / 256, 256>>>(ei, E);
    k_scan<<<1, 1024>>>();
    k_scatter<<<(tot + 255) / 256, 256>>>(ei, E);

    // Layer 1
    k_sgemm<128, 64, 16, 8, 4><<<dim3(HC1 / 64, (N_NODES + 127) / 128), 256>>>(
        N_NODES, HC1, F_IN, x, W1, p_h1);
    k_score1<<<N_NODES, 256>>>(a_src1, a_dst1);
    k_agg1<<<N_NODES, 256>>>(b1);

    // Layer 2
    k_sgemm<128, 64, 16, 8, 4><<<dim3(C2 / 64, (N_NODES + 127) / 128), 256>>>(
        N_NODES, C2, HC1, p_act1, W2, p_h2);
    k_score2<<<(N_NODES + 7) / 8, 256>>>(a_src2, a_dst2);
    k_agg2<<<N_NODES, 128>>>(b2, out);
}

// round 2
// speedup vs baseline: 1.0048x; 1.0048x over previous
#include <cuda_runtime.h>
#include <cuda_bf16.h>

// ---------------------------------------------------------------------------
// GAT 2-layer forward, GB300 (sm_103a)
// Pipeline:
//   CSR build (deg -> scan -> scatter)           [tiny]
//   GEMM1: h1 = x @ W1            [10000,256]x[256,1024]
//   score1: s_src/s_dst per (node, head)
//   agg1:  per-dst softmax + weighted gather-accumulate, +b1, ELU -> act1
//   GEMM2: h2 = act1 @ W2         [10000,1024]x[1024,128]
//   score2
//   agg2 -> d_out (+b2)
// No atomics in any hot loop; h1 (40MB) is L2-resident for the gather.
// ---------------------------------------------------------------------------

#define N_NODES 10000
#define F_IN    256
#define H1      8
#define C1      128
#define HC1     1024     // H1*C1
#define C2      128
#define E_BASE  160000
#define E_TOT   (E_BASE + N_NODES)
#define SLOPE   0.2f

// ---- device scratch (static globals; no allocation at runtime) ----
__device__ float g_h1[N_NODES * HC1];     // x @ W1
__device__ float g_act1[N_NODES * HC1];   // elu(agg1 + b1)
__device__ float g_h2[N_NODES * C2];      // act1 @ W2
__device__ float g_s1s[N_NODES * H1];
__device__ float g_s1d[N_NODES * H1];
__device__ float g_s2s[N_NODES];
__device__ float g_s2d[N_NODES];
__device__ int   g_deg[N_NODES];
__device__ int   g_rows[N_NODES + 1];
__device__ int   g_cur[N_NODES];
__device__ int   g_csr[E_TOT + 16];

// ---------------------------------------------------------------------------
// CSR build
// ---------------------------------------------------------------------------
__global__ void k_zero_deg() {
    int i = blockIdx.x * blockDim.x + threadIdx.x;
    if (i < N_NODES) g_deg[i] = 0;
}

__global__ void k_count(const int* __restrict__ ei, int E) {
    int i = blockIdx.x * blockDim.x + threadIdx.x;
    int tot = E + N_NODES;
    if (i >= tot) return;
    int dst = (i < E) ? ei[E + i] : (i - E);
    atomicAdd(&g_deg[dst], 1);
}

__global__ void k_scan() {
    __shared__ int ssum[1024];
    int tid = threadIdx.x;
    const int CH = (N_NODES + 1023) >> 10;   // 10
    int base = tid * CH;
    int s = 0;
    for (int i = 0; i < CH; i++) {
        int idx = base + i;
        if (idx < N_NODES) s += g_deg[idx];
    }
    ssum[tid] = s;
    __syncthreads();
    // Hillis-Steele inclusive scan
    for (int off = 1; off < 1024; off <<= 1) {
        int v = (tid >= off) ? ssum[tid - off] : 0;
        __syncthreads();
        ssum[tid] += v;
        __syncthreads();
    }
    int run = (tid == 0) ? 0 : ssum[tid - 1];
    for (int i = 0; i < CH; i++) {
        int idx = base + i;
        if (idx < N_NODES) {
            g_rows[idx] = run;
            g_cur[idx]  = run;
            run += g_deg[idx];
        }
    }
    if (tid == 1023) g_rows[N_NODES] = ssum[1023];
}

__global__ void k_scatter(const int* __restrict__ ei, int E) {
    int i = blockIdx.x * blockDim.x + threadIdx.x;
    int tot = E + N_NODES;
    if (i >= tot) return;
    int src = (i < E) ? ei[i]     : (i - E);
    int dst = (i < E) ? ei[E + i] : (i - E);
    int p = atomicAdd(&g_cur[dst], 1);
    g_csr[p] = src;
}

// ---------------------------------------------------------------------------
// SGEMM: C[M,N] = A[M,K] @ B[K,N], row-major, fp32.
// BM=128, BN=64, BK=16, TM=8, TN=4, 256 threads.
// N and K must be multiples of 64/16 (true here: N in {1024,128}, K in {256,1024}).
// ---------------------------------------------------------------------------
template<int BM, int BN, int BK, int TM, int TN>
__global__ __launch_bounds__(256)
void k_sgemm(int M, int N, int K,
             const float* __restrict__ A, const float* __restrict__ B,
             float* __restrict__ C) {
    __shared__ float As[BK][BM + 4];
    __shared__ float Bs[BK][BN];
    const int NT = 256;
    int bm0 = blockIdx.y * BM;
    int bn0 = blockIdx.x * BN;
    int tid = threadIdx.x;
    int tr = tid / (BN / TN);   // 0..15
    int tc = tid % (BN / TN);   // 0..15

    float acc[TM][TN];
#pragma unroll
    for (int i = 0; i < TM; i++)
#pragma unroll
        for (int j = 0; j < TN; j++) acc[i][j] = 0.f;

    for (int k0 = 0; k0 < K; k0 += BK) {
        // Load A tile: BM x BK  (float4 along K)
#pragma unroll
        for (int l = tid; l < BM * BK / 4; l += NT) {
            int row = l / (BK / 4);
            int kq  = (l % (BK / 4)) * 4;
            float4 v = make_float4(0.f, 0.f, 0.f, 0.f);
            int gm = bm0 + row;
            if (gm < M) v = *(const float4*)(A + (size_t)gm * K + k0 + kq);
            As[kq + 0][row] = v.x;
            As[kq + 1][row] = v.y;
            As[kq + 2][row] = v.z;
            As[kq + 3][row] = v.w;
        }
        // Load B tile: BK x BN
#pragma unroll
        for (int l = tid; l < BK * BN / 4; l += NT) {
            int row = l / (BN / 4);
            int nq  = (l % (BN / 4)) * 4;
            *(float4*)&Bs[row][nq] = *(const float4*)(B + (size_t)(k0 + row) * N + bn0 + nq);
        }
        __syncthreads();
#pragma unroll
        for (int k = 0; k < BK; k++) {
            float ra[TM], rb[TN];
#pragma unroll
            for (int i = 0; i < TM; i++) ra[i] = As[k][tr * TM + i];
#pragma unroll
            for (int j = 0; j < TN; j++) rb[j] = Bs[k][tc * TN + j];
#pragma unroll
            for (int i = 0; i < TM; i++)
#pragma unroll
                for (int j = 0; j < TN; j++) acc[i][j] = fmaf(ra[i], rb[j], acc[i][j]);
        }
        __syncthreads();
    }
#pragma unroll
    for (int i = 0; i < TM; i++) {
        int gm = bm0 + tr * TM + i;
        if (gm >= M) continue;
#pragma unroll
        for (int j = 0; j < TN; j += 4) {
            float4 v = make_float4(acc[i][j], acc[i][j + 1], acc[i][j + 2], acc[i][j + 3]);
            *(float4*)(C + (size_t)gm * N + bn0 + tc * TN + j) = v;
        }
    }
}

// ---------------------------------------------------------------------------
// score1: per node, per head h: s = <h1[n,h,:], a[h,:]>   (8 warps = 8 heads)
// ---------------------------------------------------------------------------
__global__ __launch_bounds__(256)
void k_score1(const float* __restrict__ a_src, const float* __restrict__ a_dst) {
    int node = blockIdx.x;
    int wid = threadIdx.x >> 5, lane = threadIdx.x & 31;
    const float* hr  = g_h1 + (size_t)node * HC1 + wid * C1;
    const float* asr = a_src + wid * C1;
    const float* adr = a_dst + wid * C1;
    float s1 = 0.f, s2 = 0.f;
#pragma unroll
    for (int j = 0; j < 4; j++) {
        int c = lane + 32 * j;
        float v = hr[c];
        s1 = fmaf(v, asr[c], s1);
        s2 = fmaf(v, adr[c], s2);
    }
#pragma unroll
    for (int o = 16; o; o >>= 1) {
        s1 += __shfl_xor_sync(~0u, s1, o);
        s2 += __shfl_xor_sync(~0u, s2, o);
    }
    if (!lane) {
        g_s1s[node * H1 + wid] = s1;
        g_s1d[node * H1 + wid] = s2;
    }
}

// ---------------------------------------------------------------------------
// agg1: one block per destination node. 256 threads.
//   pass1: per-head max over incoming edges
//   pass2: per-head softmax denom
//   pass3: chunked alpha precompute (shared) + dense float4 accumulation
//   epilogue: +b1, ELU -> g_act1
// ---------------------------------------------------------------------------
__global__ __launch_bounds__(256)
void k_agg1(const float* __restrict__ b1) {
    int n = blockIdx.x;
    int tid = threadIdx.x, wid = tid >> 5, lane = tid & 31;
    __shared__ float sdl[8], smax[8], sden[8];
    __shared__ float wr[8][8];
    __shared__ float sal[32][8];
    __shared__ int   ssrc[32];

    if (tid < 8) sdl[tid] = g_s1d[n * H1 + tid];
    int r0 = g_rows[n], r1 = g_rows[n + 1];
    int deg = r1 - r0;
    __syncthreads();

    int myh = tid & 7;
    // ---- pass 1: max per head ----
    float mx = -3.0e38f;
    for (int idx = tid; idx < deg * 8; idx += 256) {
        int s = g_csr[r0 + (idx >> 3)];
        float v = g_s1s[s * H1 + myh] + sdl[myh];
        v = v > 0.f ? v : SLOPE * v;
        mx = fmaxf(mx, v);
    }
    mx = fmaxf(mx, __shfl_xor_sync(~0u, mx, 8));
    mx = fmaxf(mx, __shfl_xor_sync(~0u, mx, 16));
    if (lane < 8) wr[wid][lane] = mx;
    __syncthreads();
    if (tid < 8) {
        float m = wr[0][tid];
#pragma unroll
        for (int w = 1; w < 8; w++) m = fmaxf(m, wr[w][tid]);
        smax[tid] = m;
    }
    __syncthreads();

    // ---- pass 2: denom per head ----
    float dn = 0.f;
    for (int idx = tid; idx < deg * 8; idx += 256) {
        int s = g_csr[r0 + (idx >> 3)];
        float v = g_s1s[s * H1 + myh] + sdl[myh];
        v = v > 0.f ? v : SLOPE * v;
        dn += __expf(v - smax[myh]);
    }
    dn += __shfl_xor_sync(~0u, dn, 8);
    dn += __shfl_xor_sync(~0u, dn, 16);
    if (lane < 8) wr[wid][lane] = dn;
    __syncthreads();
    if (tid < 8) {
        float d = 0.f;
#pragma unroll
        for (int w = 0; w < 8; w++) d += wr[w][tid];
        sden[tid] = d;
    }
    __syncthreads();

    // ---- pass 3: accumulate. thread owns channels [tid*4, tid*4+4) -> head = wid ----
    float4 acc = make_float4(0.f, 0.f, 0.f, 0.f);
    int coff = tid * 4;
    for (int e0 = r0; e0 < r1; e0 += 32) {
        int m = min(32, r1 - e0);
        if (tid < m * 8) {
            int e = e0 + (tid >> 3);
            int hh = tid & 7;
            int s = g_csr[e];
            if (hh == 0) ssrc[tid >> 3] = s;
            float v = g_s1s[s * H1 + hh] + sdl[hh];
            v = v > 0.f ? v : SLOPE * v;
            sal[tid >> 3][hh] = __expf(v - smax[hh]) / sden[hh];
        }
        __syncthreads();
        for (int j = 0; j < m; j++) {
            int s = ssrc[j];
            float a = sal[j][wid];
            float4 hv = *(const float4*)(&g_h1[(size_t)s * HC1 + coff]);
            acc.x = fmaf(hv.x, a, acc.x);
            acc.y = fmaf(hv.y, a, acc.y);
            acc.z = fmaf(hv.z, a, acc.z);
            acc.w = fmaf(hv.w, a, acc.w);
        }
        __syncthreads();
    }
    float4 bb = *(const float4*)(&b1[coff]);
    float4 o;
    float t;
    t = acc.x + bb.x; o.x = t > 0.f ? t : expm1f(t);
    t = acc.y + bb.y; o.y = t > 0.f ? t : expm1f(t);
    t = acc.z + bb.z; o.z = t > 0.f ? t : expm1f(t);
    t = acc.w + bb.w; o.w = t > 0.f ? t : expm1f(t);
    *(float4*)(&g_act1[(size_t)n * HC1 + coff]) = o;
}

// ---------------------------------------------------------------------------
// score2: 8 nodes per block (1 warp each), 128 channels, 1 head
// ---------------------------------------------------------------------------
__global__ __launch_bounds__(256)
void k_score2(const float* __restrict__ a_src, const float* __restrict__ a_dst) {
    int node = blockIdx.x * 8 + (threadIdx.x >> 5);
    int lane = threadIdx.x & 31;
    if (node >= N_NODES) return;
    const float* hr = g_h2 + (size_t)node * C2;
    float s1 = 0.f, s2 = 0.f;
#pragma unroll
    for (int j = 0; j < 4; j++) {
        int c = lane + 32 * j;
        float v = hr[c];
        s1 = fmaf(v, a_src[c], s1);
        s2 = fmaf(v, a_dst[c], s2);
    }
#pragma unroll
    for (int o = 16; o; o >>= 1) {
        s1 += __shfl_xor_sync(~0u, s1, o);
        s2 += __shfl_xor_sync(~0u, s2, o);
    }
    if (!lane) {
        g_s2s[node] = s1;
        g_s2d[node] = s2;
    }
}

// ---------------------------------------------------------------------------
// agg2: one block (128 threads) per destination node; writes final output
// ---------------------------------------------------------------------------
__global__ __launch_bounds__(128)
void k_agg2(const float* __restrict__ b2, float* __restrict__ out) {
    int n = blockIdx.x;
    int tid = threadIdx.x, wid = tid >> 5, lane = tid & 31;
    __shared__ float s_sd, s_m, s_d;
    __shared__ float wr[4];
    __shared__ float sal[64];
    __shared__ int   ssrc[64];

    if (tid == 0) s_sd = g_s2d[n];
    int r0 = g_rows[n], r1 = g_rows[n + 1];
    int deg = r1 - r0;
    __syncthreads();
    float sdv = s_sd;

    // pass 1: max
    float mx = -3.0e38f;
    for (int i = tid; i < deg; i += 128) {
        int s = g_csr[r0 + i];
        float v = g_s2s[s] + sdv;
        v = v > 0.f ? v : SLOPE * v;
        mx = fmaxf(mx, v);
    }
#pragma unroll
    for (int o = 16; o; o >>= 1) mx = fmaxf(mx, __shfl_xor_sync(~0u, mx, o));
    if (!lane) wr[wid] = mx;
    __syncthreads();
    if (tid == 0) {
        float m = wr[0];
#pragma unroll
        for (int w = 1; w < 4; w++) m = fmaxf(m, wr[w]);
        s_m = m;
    }
    __syncthreads();
    float m = s_m;

    // pass 2: denom
    float dn = 0.f;
    for (int i = tid; i < deg; i += 128) {
        int s = g_csr[r0 + i];
        float v = g_s2s[s] + sdv;
        v = v > 0.f ? v : SLOPE * v;
        dn += __expf(v - m);
    }
#pragma unroll
    for (int o = 16; o; o >>= 1) dn += __shfl_xor_sync(~0u, dn, o);
    if (!lane) wr[wid] = dn;
    __syncthreads();
    if (tid == 0) s_d = wr[0] + wr[1] + wr[2] + wr[3];
    __syncthreads();
    float den = s_d;

    // pass 3: accumulate channel tid
    float acc = 0.f;
    for (int e0 = r0; e0 < r1; e0 += 64) {
        int mc = min(64, r1 - e0);
        if (tid < mc) {
            int s = g_csr[e0 + tid];
            float v = g_s2s[s] + sdv;
            v = v > 0.f ? v : SLOPE * v;
            sal[tid] = __expf(v - m) / den;
            ssrc[tid] = s;
        }
        __syncthreads();
        for (int j = 0; j < mc; j++)
            acc = fmaf(g_h2[(size_t)ssrc[j] * C2 + tid], sal[j], acc);
        __syncthreads();
    }
    out[(size_t)n * C2 + tid] = acc + b2[tid];
}

// ---------------------------------------------------------------------------
// launch
// ---------------------------------------------------------------------------
extern "C" void kernel_launch(void* const* d_in, const int* in_sizes, int n_in,
                              void* d_out, int out_size) {
    const float* x      = (const float*)d_in[0];
    const int*   ei     = (const int*)  d_in[1];
    const float* W1     = (const float*)d_in[2];
    const float* a_src1 = (const float*)d_in[3];
    const float* a_dst1 = (const float*)d_in[4];
    const float* b1     = (const float*)d_in[5];
    const float* W2     = (const float*)d_in[6];
    const float* a_src2 = (const float*)d_in[7];
    const float* a_dst2 = (const float*)d_in[8];
    const float* b2     = (const float*)d_in[9];
    float* out = (float*)d_out;

    int E = in_sizes[1] / 2;
    int tot = E + N_NODES;

    float *p_h1, *p_act1, *p_h2;
    cudaGetSymbolAddress((void**)&p_h1,   g_h1);
    cudaGetSymbolAddress((void**)&p_act1, g_act1);
    cudaGetSymbolAddress((void**)&p_h2,   g_h2);

    // CSR build
    k_zero_deg<<<(N_NODES + 255) / 256, 256>>>();
    k_count<<<(tot + 255) / 256, 256>>>(ei, E);
    k_scan<<<1, 1024>>>();
    k_scatter<<<(tot + 255) / 256, 256>>>(ei, E);

    // Layer 1
    k_sgemm<128, 64, 16, 8, 4><<<dim3(HC1 / 64, (N_NODES + 127) / 128), 256>>>(
        N_NODES, HC1, F_IN, x, W1, p_h1);
    k_score1<<<N_NODES, 256>>>(a_src1, a_dst1);
    k_agg1<<<N_NODES, 256>>>(b1);

    // Layer 2
    k_sgemm<128, 64, 16, 8, 4><<<dim3(C2 / 64, (N_NODES + 127) / 128), 256>>>(
        N_NODES, C2, HC1, p_act1, W2, p_h2);
    k_score2<<<(N_NODES + 7) / 8, 256>>>(a_src2, a_dst2);
    k_agg2<<<N_NODES, 128>>>(b2, out);
}

// round 4
// speedup vs baseline: 1.6742x; 1.6662x over previous
#include <cuda_runtime.h>
#include <cuda_bf16.h>
#include <cstdint>

// ---------------------------------------------------------------------------
// GAT 2-layer forward, GB300 (sm_103a)
//   CSR build -> tf32 tensor-core GEMM1 -> score1 -> agg1(softmax+gather, ELU)
//   -> tf32 GEMM2 -> score2 -> agg2 -> out
// ---------------------------------------------------------------------------

#define N_NODES 10000
#define F_IN    256
#define H1      8
#define C1      128
#define HC1     1024
#define C2      128
#define E_BASE  160000
#define E_TOT   (E_BASE + N_NODES)
#define SLOPE   0.2f

__device__ float g_h1[N_NODES * HC1];
__device__ float g_act1[N_NODES * HC1];
__device__ float g_h2[N_NODES * C2];
__device__ float g_s1s[N_NODES * H1];
__device__ float g_s1d[N_NODES * H1];
__device__ float g_s2s[N_NODES];
__device__ float g_s2d[N_NODES];
__device__ int   g_deg[N_NODES];
__device__ int   g_rows[N_NODES + 1];
__device__ int   g_cur[N_NODES];
__device__ int   g_csr[E_TOT + 16];

// ---------------------------------------------------------------------------
// CSR build
// ---------------------------------------------------------------------------
__global__ void k_zero_deg() {
    int i = blockIdx.x * blockDim.x + threadIdx.x;
    if (i < N_NODES) g_deg[i] = 0;
}

__global__ void k_count(const int* __restrict__ ei, int E) {
    int i = blockIdx.x * blockDim.x + threadIdx.x;
    int tot = E + N_NODES;
    if (i >= tot) return;
    int dst = (i < E) ? ei[E + i] : (i - E);
    atomicAdd(&g_deg[dst], 1);
}

__global__ void k_scan() {
    __shared__ int ssum[1024];
    int tid = threadIdx.x;
    const int CH = (N_NODES + 1023) >> 10;
    int base = tid * CH;
    int s = 0;
    for (int i = 0; i < CH; i++) {
        int idx = base + i;
        if (idx < N_NODES) s += g_deg[idx];
    }
    ssum[tid] = s;
    __syncthreads();
    for (int off = 1; off < 1024; off <<= 1) {
        int v = (tid >= off) ? ssum[tid - off] : 0;
        __syncthreads();
        ssum[tid] += v;
        __syncthreads();
    }
    int run = (tid == 0) ? 0 : ssum[tid - 1];
    for (int i = 0; i < CH; i++) {
        int idx = base + i;
        if (idx < N_NODES) {
            g_rows[idx] = run;
            g_cur[idx]  = run;
            run += g_deg[idx];
        }
    }
    if (tid == 1023) g_rows[N_NODES] = ssum[1023];
}

__global__ void k_scatter(const int* __restrict__ ei, int E) {
    int i = blockIdx.x * blockDim.x + threadIdx.x;
    int tot = E + N_NODES;
    if (i >= tot) return;
    int src = (i < E) ? ei[i]     : (i - E);
    int dst = (i < E) ? ei[E + i] : (i - E);
    int p = atomicAdd(&g_cur[dst], 1);
    g_csr[p] = src;
}

// ---------------------------------------------------------------------------
// tf32 tensor-core GEMM: C[M,N] = A[M,K] @ B[K,N], row-major fp32 in/out.
// BN=128, BK=16, WN=32 fixed; 8 warps (2 x 4). N%128==0, K%16==0 required.
// A-frag smem stride 20 words -> bank == lane (conflict-free).
// B-frag smem stride 136 words -> bank == 8*k + n (conflict-free).
// ---------------------------------------------------------------------------
__device__ __forceinline__ uint32_t f2tf32(float f) {
    uint32_t u;
    asm("cvt.rna.tf32.f32 %0, %1;" : "=r"(u) : "f"(f));
    return u;
}

__device__ __forceinline__ void mma_tf32(float* c, const uint32_t* a, const uint32_t* b) {
    asm volatile(
        "mma.sync.aligned.m16n8k8.row.col.f32.tf32.tf32.f32 "
        "{%0,%1,%2,%3}, {%4,%5,%6,%7}, {%8,%9}, {%0,%1,%2,%3};"
        : "+f"(c[0]), "+f"(c[1]), "+f"(c[2]), "+f"(c[3])
        : "r"(a[0]), "r"(a[1]), "r"(a[2]), "r"(a[3]), "r"(b[0]), "r"(b[1]));
}

template<int BM, int WM>
__global__ __launch_bounds__(256)
void k_mma_gemm(int M, int N, int K,
                const float* __restrict__ A, const float* __restrict__ B,
                float* __restrict__ C) {
    constexpr int BN = 128, BK = 16;
    constexpr int SA = 20, SB = 136;
    constexpr int MT = WM / 16;
    constexpr int AR = BM / 64;        // float4 A-loads per thread per tile

    __shared__ uint32_t As[2][BM * SA];
    __shared__ uint32_t Bs[2][BK * SB];

    int tid = threadIdx.x, wid = tid >> 5, lane = tid & 31;
    int bm0 = blockIdx.y * BM, bn0 = blockIdx.x * BN;
    int wm = (wid >> 2) * WM, wn = (wid & 3) * 32;

    float acc[MT][4][4];
#pragma unroll
    for (int i = 0; i < MT; i++)
#pragma unroll
        for (int j = 0; j < 4; j++)
#pragma unroll
            for (int l = 0; l < 4; l++) acc[i][j][l] = 0.f;

    // A tile: BM x 16; thread -> row tid/4 (+64*i), kchunk (tid%4)*4
    int a_row = tid >> 2, a_col = (tid & 3) * 4;
    // B tile: 16 x 128; thread -> row tid/32 (+8*i), col chunk (tid%32)*4
    int b_row = tid >> 5, b_col = (tid & 31) * 4;

    float4 ra[AR], rb[2];

    auto ldg = [&](int k0) {
#pragma unroll
        for (int i = 0; i < AR; i++) {
            int r = bm0 + a_row + i * 64;
            ra[i] = (r < M) ? *(const float4*)(A + (size_t)r * K + k0 + a_col)
                            : make_float4(0.f, 0.f, 0.f, 0.f);
        }
#pragma unroll
        for (int i = 0; i < 2; i++)
            rb[i] = *(const float4*)(B + (size_t)(k0 + b_row + i * 8) * N + bn0 + b_col);
    };
    auto sts = [&](int buf) {
#pragma unroll
        for (int i = 0; i < AR; i++) {
            uint4 v;
            v.x = f2tf32(ra[i].x); v.y = f2tf32(ra[i].y);
            v.z = f2tf32(ra[i].z); v.w = f2tf32(ra[i].w);
            *(uint4*)&As[buf][(a_row + i * 64) * SA + a_col] = v;
        }
#pragma unroll
        for (int i = 0; i < 2; i++) {
            uint4 v;
            v.x = f2tf32(rb[i].x); v.y = f2tf32(rb[i].y);
            v.z = f2tf32(rb[i].z); v.w = f2tf32(rb[i].w);
            *(uint4*)&Bs[buf][(b_row + i * 8) * SB + b_col] = v;
        }
    };
    auto compute = [&](int buf) {
#pragma unroll
        for (int ks = 0; ks < 2; ks++) {
            int k = ks * 8;
            uint32_t af[MT][4], bf[4][2];
#pragma unroll
            for (int mt = 0; mt < MT; mt++) {
                int r = wm + mt * 16 + (lane >> 2);
                int kc = k + (lane & 3);
                af[mt][0] = As[buf][r * SA + kc];
                af[mt][1] = As[buf][(r + 8) * SA + kc];
                af[mt][2] = As[buf][r * SA + kc + 4];
                af[mt][3] = As[buf][(r + 8) * SA + kc + 4];
            }
#pragma unroll
            for (int nt = 0; nt < 4; nt++) {
                int c = wn + nt * 8 + (lane >> 2);
                int kr = k + (lane & 3);
                bf[nt][0] = Bs[buf][kr * SB + c];
                bf[nt][1] = Bs[buf][(kr + 4) * SB + c];
            }
#pragma unroll
            for (int mt = 0; mt < MT; mt++)
#pragma unroll
                for (int nt = 0; nt < 4; nt++)
                    mma_tf32(acc[mt][nt], af[mt], bf[nt]);
        }
    };

    ldg(0);
    sts(0);
    __syncthreads();
    int iters = K / BK;
    for (int it = 0; it < iters; it++) {
        int cur = it & 1;
        if (it + 1 < iters) ldg((it + 1) * BK);
        compute(cur);
        if (it + 1 < iters) {
            sts(cur ^ 1);
            __syncthreads();
        }
    }

#pragma unroll
    for (int mt = 0; mt < MT; mt++) {
        int r = bm0 + wm + mt * 16 + (lane >> 2);
#pragma unroll
        for (int nt = 0; nt < 4; nt++) {
            int c = bn0 + wn + nt * 8 + (lane & 3) * 2;
            if (r < M)
                *(float2*)(C + (size_t)r * N + c) =
                    make_float2(acc[mt][nt][0], acc[mt][nt][1]);
            if (r + 8 < M)
                *(float2*)(C + (size_t)(r + 8) * N + c) =
                    make_float2(acc[mt][nt][2], acc[mt][nt][3]);
        }
    }
}

// ---------------------------------------------------------------------------
// score1
// ---------------------------------------------------------------------------
__global__ __launch_bounds__(256)
void k_score1(const float* __restrict__ a_src, const float* __restrict__ a_dst) {
    int node = blockIdx.x;
    int wid = threadIdx.x >> 5, lane = threadIdx.x & 31;
    const float* hr  = g_h1 + (size_t)node * HC1 + wid * C1;
    const float* asr = a_src + wid * C1;
    const float* adr = a_dst + wid * C1;
    float s1 = 0.f, s2 = 0.f;
#pragma unroll
    for (int j = 0; j < 4; j++) {
        int c = lane + 32 * j;
        float v = hr[c];
        s1 = fmaf(v, asr[c], s1);
        s2 = fmaf(v, adr[c], s2);
    }
#pragma unroll
    for (int o = 16; o; o >>= 1) {
        s1 += __shfl_xor_sync(~0u, s1, o);
        s2 += __shfl_xor_sync(~0u, s2, o);
    }
    if (!lane) {
        g_s1s[node * H1 + wid] = s1;
        g_s1d[node * H1 + wid] = s2;
    }
}

// ---------------------------------------------------------------------------
// agg1: per-dst softmax + gather-accumulate, +b1, ELU
// ---------------------------------------------------------------------------
__global__ __launch_bounds__(256)
void k_agg1(const float* __restrict__ b1) {
    int n = blockIdx.x;
    int tid = threadIdx.x, wid = tid >> 5, lane = tid & 31;
    __shared__ float sdl[8], smax[8], sden[8];
    __shared__ float wr[8][8];
    __shared__ float sal[32][8];
    __shared__ int   ssrc[32];

    if (tid < 8) sdl[tid] = g_s1d[n * H1 + tid];
    int r0 = g_rows[n], r1 = g_rows[n + 1];
    int deg = r1 - r0;
    __syncthreads();

    int myh = tid & 7;
    float mx = -3.0e38f;
    for (int idx = tid; idx < deg * 8; idx += 256) {
        int s = g_csr[r0 + (idx >> 3)];
        float v = g_s1s[s * H1 + myh] + sdl[myh];
        v = v > 0.f ? v : SLOPE * v;
        mx = fmaxf(mx, v);
    }
    mx = fmaxf(mx, __shfl_xor_sync(~0u, mx, 8));
    mx = fmaxf(mx, __shfl_xor_sync(~0u, mx, 16));
    if (lane < 8) wr[wid][lane] = mx;
    __syncthreads();
    if (tid < 8) {
        float m = wr[0][tid];
#pragma unroll
        for (int w = 1; w < 8; w++) m = fmaxf(m, wr[w][tid]);
        smax[tid] = m;
    }
    __syncthreads();

    float dn = 0.f;
    for (int idx = tid; idx < deg * 8; idx += 256) {
        int s = g_csr[r0 + (idx >> 3)];
        float v = g_s1s[s * H1 + myh] + sdl[myh];
        v = v > 0.f ? v : SLOPE * v;
        dn += __expf(v - smax[myh]);
    }
    dn += __shfl_xor_sync(~0u, dn, 8);
    dn += __shfl_xor_sync(~0u, dn, 16);
    if (lane < 8) wr[wid][lane] = dn;
    __syncthreads();
    if (tid < 8) {
        float d = 0.f;
#pragma unroll
        for (int w = 0; w < 8; w++) d += wr[w][tid];
        sden[tid] = d;
    }
    __syncthreads();

    float4 acc = make_float4(0.f, 0.f, 0.f, 0.f);
    int coff = tid * 4;
    for (int e0 = r0; e0 < r1; e0 += 32) {
        int m = min(32, r1 - e0);
        if (tid < m * 8) {
            int e = e0 + (tid >> 3);
            int hh = tid & 7;
            int s = g_csr[e];
            if (hh == 0) ssrc[tid >> 3] = s;
            float v = g_s1s[s * H1 + hh] + sdl[hh];
            v = v > 0.f ? v : SLOPE * v;
            sal[tid >> 3][hh] = __expf(v - smax[hh]) / sden[hh];
        }
        __syncthreads();
        for (int j = 0; j < m; j++) {
            int s = ssrc[j];
            float a = sal[j][wid];
            float4 hv = *(const float4*)(&g_h1[(size_t)s * HC1 + coff]);
            acc.x = fmaf(hv.x, a, acc.x);
            acc.y = fmaf(hv.y, a, acc.y);
            acc.z = fmaf(hv.z, a, acc.z);
            acc.w = fmaf(hv.w, a, acc.w);
        }
        __syncthreads();
    }
    float4 bb = *(const float4*)(&b1[coff]);
    float4 o;
    float t;
    t = acc.x + bb.x; o.x = t > 0.f ? t : expm1f(t);
    t = acc.y + bb.y; o.y = t > 0.f ? t : expm1f(t);
    t = acc.z + bb.z; o.z = t > 0.f ? t : expm1f(t);
    t = acc.w + bb.w; o.w = t > 0.f ? t : expm1f(t);
    *(float4*)(&g_act1[(size_t)n * HC1 + coff]) = o;
}

// ---------------------------------------------------------------------------
// score2
// ---------------------------------------------------------------------------
__global__ __launch_bounds__(256)
void k_score2(const float* __restrict__ a_src, const float* __restrict__ a_dst) {
    int node = blockIdx.x * 8 + (threadIdx.x >> 5);
    int lane = threadIdx.x & 31;
    if (node >= N_NODES) return;
    const float* hr = g_h2 + (size_t)node * C2;
    float s1 = 0.f, s2 = 0.f;
#pragma unroll
    for (int j = 0; j < 4; j++) {
        int c = lane + 32 * j;
        float v = hr[c];
        s1 = fmaf(v, a_src[c], s1);
        s2 = fmaf(v, a_dst[c], s2);
    }
#pragma unroll
    for (int o = 16; o; o >>= 1) {
        s1 += __shfl_xor_sync(~0u, s1, o);
        s2 += __shfl_xor_sync(~0u, s2, o);
    }
    if (!lane) {
        g_s2s[node] = s1;
        g_s2d[node] = s2;
    }
}

// ---------------------------------------------------------------------------
// agg2
// ---------------------------------------------------------------------------
__global__ __launch_bounds__(128)
void k_agg2(const float* __restrict__ b2, float* __restrict__ out) {
    int n = blockIdx.x;
    int tid = threadIdx.x, wid = tid >> 5, lane = tid & 31;
    __shared__ float s_sd, s_m, s_d;
    __shared__ float wr[4];
    __shared__ float sal[64];
    __shared__ int   ssrc[64];

    if (tid == 0) s_sd = g_s2d[n];
    int r0 = g_rows[n], r1 = g_rows[n + 1];
    int deg = r1 - r0;
    __syncthreads();
    float sdv = s_sd;

    float mx = -3.0e38f;
    for (int i = tid; i < deg; i += 128) {
        int s = g_csr[r0 + i];
        float v = g_s2s[s] + sdv;
        v = v > 0.f ? v : SLOPE * v;
        mx = fmaxf(mx, v);
    }
#pragma unroll
    for (int o = 16; o; o >>= 1) mx = fmaxf(mx, __shfl_xor_sync(~0u, mx, o));
    if (!lane) wr[wid] = mx;
    __syncthreads();
    if (tid == 0) {
        float m = wr[0];
#pragma unroll
        for (int w = 1; w < 4; w++) m = fmaxf(m, wr[w]);
        s_m = m;
    }
    __syncthreads();
    float m = s_m;

    float dn = 0.f;
    for (int i = tid; i < deg; i += 128) {
        int s = g_csr[r0 + i];
        float v = g_s2s[s] + sdv;
        v = v > 0.f ? v : SLOPE * v;
        dn += __expf(v - m);
    }
#pragma unroll
    for (int o = 16; o; o >>= 1) dn += __shfl_xor_sync(~0u, dn, o);
    if (!lane) wr[wid] = dn;
    __syncthreads();
    if (tid == 0) s_d = wr[0] + wr[1] + wr[2] + wr[3];
    __syncthreads();
    float den = s_d;

    float acc = 0.f;
    for (int e0 = r0; e0 < r1; e0 += 64) {
        int mc = min(64, r1 - e0);
        if (tid < mc) {
            int s = g_csr[e0 + tid];
            float v = g_s2s[s] + sdv;
            v = v > 0.f ? v : SLOPE * v;
            sal[tid] = __expf(v - m) / den;
            ssrc[tid] = s;
        }
        __syncthreads();
        for (int j = 0; j < mc; j++)
            acc = fmaf(g_h2[(size_t)ssrc[j] * C2 + tid], sal[j], acc);
        __syncthreads();
    }
    out[(size_t)n * C2 + tid] = acc + b2[tid];
}

// ---------------------------------------------------------------------------
// launch
// ---------------------------------------------------------------------------
extern "C" void kernel_launch(void* const* d_in, const int* in_sizes, int n_in,
                              void* d_out, int out_size) {
    const float* x      = (const float*)d_in[0];
    const int*   ei     = (const int*)  d_in[1];
    const float* W1     = (const float*)d_in[2];
    const float* a_src1 = (const float*)d_in[3];
    const float* a_dst1 = (const float*)d_in[4];
    const float* b1     = (const float*)d_in[5];
    const float* W2     = (const float*)d_in[6];
    const float* a_src2 = (const float*)d_in[7];
    const float* a_dst2 = (const float*)d_in[8];
    const float* b2     = (const float*)d_in[9];
    float* out = (float*)d_out;

    int E = in_sizes[1] / 2;
    int tot = E + N_NODES;

    float *p_h1, *p_act1, *p_h2;
    cudaGetSymbolAddress((void**)&p_h1,   g_h1);
    cudaGetSymbolAddress((void**)&p_act1, g_act1);
    cudaGetSymbolAddress((void**)&p_h2,   g_h2);

    // CSR build
    k_zero_deg<<<(N_NODES + 255) / 256, 256>>>();
    k_count<<<(tot + 255) / 256, 256>>>(ei, E);
    k_scan<<<1, 1024>>>();
    k_scatter<<<(tot + 255) / 256, 256>>>(ei, E);

    // Layer 1: tf32 tensor-core GEMM (BM=128, WM=64)
    k_mma_gemm<128, 64><<<dim3(HC1 / 128, (N_NODES + 127) / 128), 256>>>(
        N_NODES, HC1, F_IN, x, W1, p_h1);
    k_score1<<<N_NODES, 256>>>(a_src1, a_dst1);
    k_agg1<<<N_NODES, 256>>>(b1);

    // Layer 2: tf32 tensor-core GEMM (BM=64, WM=32 -> 157 blocks)
    k_mma_gemm<64, 32><<<dim3(C2 / 128, (N_NODES + 63) / 64), 256>>>(
        N_NODES, C2, HC1, p_act1, W2, p_h2);
    k_score2<<<(N_NODES + 7) / 8, 256>>>(a_src2, a_dst2);
    k_agg2<<<N_NODES, 128>>>(b2, out);
}

// round 5
// speedup vs baseline: 1.7762x; 1.0609x over previous
#include <cuda_runtime.h>
#include <cuda_bf16.h>
#include <cuda_fp16.h>
#include <cstdint>

// ---------------------------------------------------------------------------
// GAT 2-layer forward, GB300 (sm_103a)
//   CSR build -> tf32 MMA GEMM1 -> score1(+fp16 mirror) -> agg1(online softmax,
//   fp16 gather, ELU) -> tf32 GEMM2 -> score2 -> agg2 -> out
// ---------------------------------------------------------------------------

#define N_NODES 10000
#define F_IN    256
#define H1      8
#define C1      128
#define HC1     1024
#define C2      128
#define E_BASE  160000
#define E_TOT   (E_BASE + N_NODES)
#define SLOPE   0.2f

__device__ float  g_h1[N_NODES * HC1];
__device__ __half g_h1h[N_NODES * HC1];
__device__ float  g_act1[N_NODES * HC1];
__device__ float  g_h2[N_NODES * C2];
__device__ float  g_s1s[N_NODES * H1];
__device__ float  g_s1d[N_NODES * H1];
__device__ float  g_s2s[N_NODES];
__device__ float  g_s2d[N_NODES];
__device__ int    g_deg[N_NODES];
__device__ int    g_rows[N_NODES + 1];
__device__ int    g_cur[N_NODES];
__device__ int    g_csr[E_TOT + 16];

// ---------------------------------------------------------------------------
// CSR build
// ---------------------------------------------------------------------------
__global__ void k_count(const int* __restrict__ ei, int E) {
    int i = blockIdx.x * blockDim.x + threadIdx.x;
    int tot = E + N_NODES;
    if (i >= tot) return;
    int dst = (i < E) ? ei[E + i] : (i - E);
    atomicAdd(&g_deg[dst], 1);
}

__global__ void k_scan() {
    __shared__ int ssum[1024];
    int tid = threadIdx.x;
    const int CH = (N_NODES + 1023) >> 10;
    int base = tid * CH;
    int s = 0;
    for (int i = 0; i < CH; i++) {
        int idx = base + i;
        if (idx < N_NODES) s += g_deg[idx];
    }
    ssum[tid] = s;
    __syncthreads();
    for (int off = 1; off < 1024; off <<= 1) {
        int v = (tid >= off) ? ssum[tid - off] : 0;
        __syncthreads();
        ssum[tid] += v;
        __syncthreads();
    }
    int run = (tid == 0) ? 0 : ssum[tid - 1];
    for (int i = 0; i < CH; i++) {
        int idx = base + i;
        if (idx < N_NODES) {
            g_rows[idx] = run;
            g_cur[idx]  = run;
            run += g_deg[idx];
        }
    }
    if (tid == 1023) g_rows[N_NODES] = ssum[1023];
}

__global__ void k_scatter(const int* __restrict__ ei, int E) {
    int i = blockIdx.x * blockDim.x + threadIdx.x;
    int tot = E + N_NODES;
    if (i >= tot) return;
    int src = (i < E) ? ei[i]     : (i - E);
    int dst = (i < E) ? ei[E + i] : (i - E);
    int p = atomicAdd(&g_cur[dst], 1);
    g_csr[p] = src;
}

// ---------------------------------------------------------------------------
// tf32 tensor-core GEMM: C[M,N] = A[M,K] @ B[K,N], row-major fp32 in/out.
// ---------------------------------------------------------------------------
__device__ __forceinline__ uint32_t f2tf32(float f) {
    uint32_t u;
    asm("cvt.rna.tf32.f32 %0, %1;" : "=r"(u) : "f"(f));
    return u;
}

__device__ __forceinline__ void mma_tf32(float* c, const uint32_t* a, const uint32_t* b) {
    asm volatile(
        "mma.sync.aligned.m16n8k8.row.col.f32.tf32.tf32.f32 "
        "{%0,%1,%2,%3}, {%4,%5,%6,%7}, {%8,%9}, {%0,%1,%2,%3};"
        : "+f"(c[0]), "+f"(c[1]), "+f"(c[2]), "+f"(c[3])
        : "r"(a[0]), "r"(a[1]), "r"(a[2]), "r"(a[3]), "r"(b[0]), "r"(b[1]));
}

template<int BM, int WM>
__global__ __launch_bounds__(256)
void k_mma_gemm(int M, int N, int K,
                const float* __restrict__ A, const float* __restrict__ B,
                float* __restrict__ C) {
    constexpr int BN = 128, BK = 16;
    constexpr int SA = 20, SB = 136;
    constexpr int MT = WM / 16;
    constexpr int AR = BM / 64;

    __shared__ uint32_t As[2][BM * SA];
    __shared__ uint32_t Bs[2][BK * SB];

    int tid = threadIdx.x, wid = tid >> 5, lane = tid & 31;
    int bm0 = blockIdx.y * BM, bn0 = blockIdx.x * BN;
    int wm = (wid >> 2) * WM, wn = (wid & 3) * 32;

    float acc[MT][4][4];
#pragma unroll
    for (int i = 0; i < MT; i++)
#pragma unroll
        for (int j = 0; j < 4; j++)
#pragma unroll
            for (int l = 0; l < 4; l++) acc[i][j][l] = 0.f;

    int a_row = tid >> 2, a_col = (tid & 3) * 4;
    int b_row = tid >> 5, b_col = (tid & 31) * 4;

    float4 ra[AR], rb[2];

    auto ldg = [&](int k0) {
#pragma unroll
        for (int i = 0; i < AR; i++) {
            int r = bm0 + a_row + i * 64;
            ra[i] = (r < M) ? *(const float4*)(A + (size_t)r * K + k0 + a_col)
                            : make_float4(0.f, 0.f, 0.f, 0.f);
        }
#pragma unroll
        for (int i = 0; i < 2; i++)
            rb[i] = *(const float4*)(B + (size_t)(k0 + b_row + i * 8) * N + bn0 + b_col);
    };
    auto sts = [&](int buf) {
#pragma unroll
        for (int i = 0; i < AR; i++) {
            uint4 v;
            v.x = f2tf32(ra[i].x); v.y = f2tf32(ra[i].y);
            v.z = f2tf32(ra[i].z); v.w = f2tf32(ra[i].w);
            *(uint4*)&As[buf][(a_row + i * 64) * SA + a_col] = v;
        }
#pragma unroll
        for (int i = 0; i < 2; i++) {
            uint4 v;
            v.x = f2tf32(rb[i].x); v.y = f2tf32(rb[i].y);
            v.z = f2tf32(rb[i].z); v.w = f2tf32(rb[i].w);
            *(uint4*)&Bs[buf][(b_row + i * 8) * SB + b_col] = v;
        }
    };
    auto compute = [&](int buf) {
#pragma unroll
        for (int ks = 0; ks < 2; ks++) {
            int k = ks * 8;
            uint32_t af[MT][4], bf[4][2];
#pragma unroll
            for (int mt = 0; mt < MT; mt++) {
                int r = wm + mt * 16 + (lane >> 2);
                int kc = k + (lane & 3);
                af[mt][0] = As[buf][r * SA + kc];
                af[mt][1] = As[buf][(r + 8) * SA + kc];
                af[mt][2] = As[buf][r * SA + kc + 4];
                af[mt][3] = As[buf][(r + 8) * SA + kc + 4];
            }
#pragma unroll
            for (int nt = 0; nt < 4; nt++) {
                int c = wn + nt * 8 + (lane >> 2);
                int kr = k + (lane & 3);
                bf[nt][0] = Bs[buf][kr * SB + c];
                bf[nt][1] = Bs[buf][(kr + 4) * SB + c];
            }
#pragma unroll
            for (int mt = 0; mt < MT; mt++)
#pragma unroll
                for (int nt = 0; nt < 4; nt++)
                    mma_tf32(acc[mt][nt], af[mt], bf[nt]);
        }
    };

    ldg(0);
    sts(0);
    __syncthreads();
    int iters = K / BK;
    for (int it = 0; it < iters; it++) {
        int cur = it & 1;
        if (it + 1 < iters) ldg((it + 1) * BK);
        compute(cur);
        if (it + 1 < iters) {
            sts(cur ^ 1);
            __syncthreads();
        }
    }

#pragma unroll
    for (int mt = 0; mt < MT; mt++) {
        int r = bm0 + wm + mt * 16 + (lane >> 2);
#pragma unroll
        for (int nt = 0; nt < 4; nt++) {
            int c = bn0 + wn + nt * 8 + (lane & 3) * 2;
            if (r < M)
                *(float2*)(C + (size_t)r * N + c) =
                    make_float2(acc[mt][nt][0], acc[mt][nt][1]);
            if (r + 8 < M)
                *(float2*)(C + (size_t)(r + 8) * N + c) =
                    make_float2(acc[mt][nt][2], acc[mt][nt][3]);
        }
    }
}

// ---------------------------------------------------------------------------
// score1: per node/head dot products; also writes fp16 mirror of h1.
// One block per node; warp = head; lane handles 4 contiguous channels.
// ---------------------------------------------------------------------------
__global__ __launch_bounds__(256)
void k_score1(const float* __restrict__ a_src, const float* __restrict__ a_dst) {
    int node = blockIdx.x;
    int wid = threadIdx.x >> 5, lane = threadIdx.x & 31;
    size_t off = (size_t)node * HC1 + wid * C1 + lane * 4;
    float4 v = *(const float4*)(g_h1 + off);

    // fp16 mirror (coalesced 8B per lane)
    __half2 p0 = __floats2half2_rn(v.x, v.y);
    __half2 p1 = __floats2half2_rn(v.z, v.w);
    uint2 u;
    u.x = *(uint32_t*)&p0;
    u.y = *(uint32_t*)&p1;
    *(uint2*)(g_h1h + off) = u;

    float4 as = *(const float4*)(a_src + wid * C1 + lane * 4);
    float4 ad = *(const float4*)(a_dst + wid * C1 + lane * 4);
    float s1 = v.x * as.x + v.y * as.y + v.z * as.z + v.w * as.w;
    float s2 = v.x * ad.x + v.y * ad.y + v.z * ad.z + v.w * ad.w;
#pragma unroll
    for (int o = 16; o; o >>= 1) {
        s1 += __shfl_xor_sync(~0u, s1, o);
        s2 += __shfl_xor_sync(~0u, s2, o);
    }
    if (!lane) {
        g_s1s[node * H1 + wid] = s1;
        g_s1d[node * H1 + wid] = s2;
    }
}

// ---------------------------------------------------------------------------
// agg1: one block (128 thr) per dst node.
//   pass A: online softmax (max+sum fused) per head
//   pass B: chunked alpha + fp16 gather, fp32 accumulate; +b1, ELU
// thread owns channels [tid*8, tid*8+8) -> head = tid/16
// ---------------------------------------------------------------------------
__global__ __launch_bounds__(128)
void k_agg1(const float* __restrict__ b1) {
    int n = blockIdx.x;
    int tid = threadIdx.x, wid = tid >> 5, lane = tid & 31;
    __shared__ float  sdl[8], smax[8], sden[8];
    __shared__ float2 wr[4][8];
    __shared__ float  sal[16][8];
    __shared__ int    ssrc[16];

    if (tid < 8) sdl[tid] = g_s1d[n * H1 + tid];
    int r0 = g_rows[n], r1 = g_rows[n + 1];
    int deg = r1 - r0;
    __syncthreads();

    int myh = tid & 7;
    float sdh = sdl[myh];

    // ---- pass A: fused online max/sum per head ----
    float m = -3.0e38f, s = 0.f;
    for (int idx = tid; idx < deg * 8; idx += 128) {
        int src = g_csr[r0 + (idx >> 3)];
        float v = g_s1s[src * H1 + myh] + sdh;
        v = v > 0.f ? v : SLOPE * v;
        float nm = fmaxf(m, v);
        s = s * __expf(m - nm) + __expf(v - nm);
        m = nm;
    }
#pragma unroll
    for (int o = 8; o <= 16; o <<= 1) {
        float om = __shfl_xor_sync(~0u, m, o);
        float os = __shfl_xor_sync(~0u, s, o);
        float nm = fmaxf(m, om);
        s = s * __expf(m - nm) + os * __expf(om - nm);
        m = nm;
    }
    if (lane < 8) wr[wid][lane] = make_float2(m, s);
    __syncthreads();
    if (tid < 8) {
        float M = wr[0][tid].x, S = wr[0][tid].y;
#pragma unroll
        for (int w = 1; w < 4; w++) {
            float m2 = wr[w][tid].x, s2 = wr[w][tid].y;
            float nm = fmaxf(M, m2);
            S = S * __expf(M - nm) + s2 * __expf(m2 - nm);
            M = nm;
        }
        smax[tid] = M;
        sden[tid] = 1.f / S;
    }
    __syncthreads();

    // ---- pass B: gather-accumulate ----
    float acc[8];
#pragma unroll
    for (int k = 0; k < 8; k++) acc[k] = 0.f;
    int c0 = tid * 8;
    int hown = tid >> 4;

    for (int e0 = r0; e0 < r1; e0 += 16) {
        int mc = min(16, r1 - e0);
        if (tid < mc * 8) {
            int e = e0 + (tid >> 3);
            int h = tid & 7;
            int src = g_csr[e];
            if (h == 0) ssrc[tid >> 3] = src;
            float v = g_s1s[src * H1 + h] + sdl[h];
            v = v > 0.f ? v : SLOPE * v;
            sal[tid >> 3][h] = __expf(v - smax[h]) * sden[h];
        }
        __syncthreads();
        for (int j = 0; j < mc; j++) {
            int src = ssrc[j];
            float a = sal[j][hown];
            uint4 u = *(const uint4*)(g_h1h + (size_t)src * HC1 + c0);
            float2 f0 = __half22float2(*(__half2*)&u.x);
            float2 f1 = __half22float2(*(__half2*)&u.y);
            float2 f2 = __half22float2(*(__half2*)&u.z);
            float2 f3 = __half22float2(*(__half2*)&u.w);
            acc[0] = fmaf(f0.x, a, acc[0]); acc[1] = fmaf(f0.y, a, acc[1]);
            acc[2] = fmaf(f1.x, a, acc[2]); acc[3] = fmaf(f1.y, a, acc[3]);
            acc[4] = fmaf(f2.x, a, acc[4]); acc[5] = fmaf(f2.y, a, acc[5]);
            acc[6] = fmaf(f3.x, a, acc[6]); acc[7] = fmaf(f3.y, a, acc[7]);
        }
        __syncthreads();
    }

    float out[8];
#pragma unroll
    for (int k = 0; k < 8; k++) {
        float t = acc[k] + b1[c0 + k];
        out[k] = t > 0.f ? t : expm1f(t);
    }
    *(float4*)(g_act1 + (size_t)n * HC1 + c0)     = make_float4(out[0], out[1], out[2], out[3]);
    *(float4*)(g_act1 + (size_t)n * HC1 + c0 + 4) = make_float4(out[4], out[5], out[6], out[7]);
}

// ---------------------------------------------------------------------------
// score2: 8 nodes per block (1 warp each)
// ---------------------------------------------------------------------------
__global__ __launch_bounds__(256)
void k_score2(const float* __restrict__ a_src, const float* __restrict__ a_dst) {
    int node = blockIdx.x * 8 + (threadIdx.x >> 5);
    int lane = threadIdx.x & 31;
    if (node >= N_NODES) return;
    const float* hr = g_h2 + (size_t)node * C2;
    float4 v = *(const float4*)(hr + lane * 4);
    float4 as = *(const float4*)(a_src + lane * 4);
    float4 ad = *(const float4*)(a_dst + lane * 4);
    float s1 = v.x * as.x + v.y * as.y + v.z * as.z + v.w * as.w;
    float s2 = v.x * ad.x + v.y * ad.y + v.z * ad.z + v.w * ad.w;
#pragma unroll
    for (int o = 16; o; o >>= 1) {
        s1 += __shfl_xor_sync(~0u, s1, o);
        s2 += __shfl_xor_sync(~0u, s2, o);
    }
    if (!lane) {
        g_s2s[node] = s1;
        g_s2d[node] = s2;
    }
}

// ---------------------------------------------------------------------------
// agg2: one block (128 thr) per dst node; online softmax; fp32 gather.
// ---------------------------------------------------------------------------
__global__ __launch_bounds__(128)
void k_agg2(const float* __restrict__ b2, float* __restrict__ out) {
    int n = blockIdx.x;
    int tid = threadIdx.x, wid = tid >> 5, lane = tid & 31;
    __shared__ float s_sd, s_m, s_d;
    __shared__ float2 wr[4];
    __shared__ float sal[64];
    __shared__ int   ssrc[64];

    if (tid == 0) s_sd = g_s2d[n];
    int r0 = g_rows[n], r1 = g_rows[n + 1];
    int deg = r1 - r0;
    __syncthreads();
    float sdv = s_sd;

    // fused online max/sum
    float m = -3.0e38f, s = 0.f;
    for (int i = tid; i < deg; i += 128) {
        int src = g_csr[r0 + i];
        float v = g_s2s[src] + sdv;
        v = v > 0.f ? v : SLOPE * v;
        float nm = fmaxf(m, v);
        s = s * __expf(m - nm) + __expf(v - nm);
        m = nm;
    }
#pragma unroll
    for (int o = 16; o; o >>= 1) {
        float om = __shfl_xor_sync(~0u, m, o);
        float os = __shfl_xor_sync(~0u, s, o);
        float nm = fmaxf(m, om);
        s = s * __expf(m - nm) + os * __expf(om - nm);
        m = nm;
    }
    if (!lane) wr[wid] = make_float2(m, s);
    __syncthreads();
    if (tid == 0) {
        float M = wr[0].x, S = wr[0].y;
#pragma unroll
        for (int w = 1; w < 4; w++) {
            float m2 = wr[w].x, s2 = wr[w].y;
            float nm = fmaxf(M, m2);
            S = S * __expf(M - nm) + s2 * __expf(m2 - nm);
            M = nm;
        }
        s_m = M;
        s_d = 1.f / S;
    }
    __syncthreads();
    float M = s_m, inv = s_d;

    float acc = 0.f;
    for (int e0 = r0; e0 < r1; e0 += 64) {
        int mc = min(64, r1 - e0);
        if (tid < mc) {
            int src = g_csr[e0 + tid];
            float v = g_s2s[src] + sdv;
            v = v > 0.f ? v : SLOPE * v;
            sal[tid] = __expf(v - M) * inv;
            ssrc[tid] = src;
        }
        __syncthreads();
        for (int j = 0; j < mc; j++)
            acc = fmaf(g_h2[(size_t)ssrc[j] * C2 + tid], sal[j], acc);
        __syncthreads();
    }
    out[(size_t)n * C2 + tid] = acc + b2[tid];
}

// ---------------------------------------------------------------------------
// launch
// ---------------------------------------------------------------------------
extern "C" void kernel_launch(void* const* d_in, const int* in_sizes, int n_in,
                              void* d_out, int out_size) {
    const float* x      = (const float*)d_in[0];
    const int*   ei     = (const int*)  d_in[1];
    const float* W1     = (const float*)d_in[2];
    const float* a_src1 = (const float*)d_in[3];
    const float* a_dst1 = (const float*)d_in[4];
    const float* b1     = (const float*)d_in[5];
    const float* W2     = (const float*)d_in[6];
    const float* a_src2 = (const float*)d_in[7];
    const float* a_dst2 = (const float*)d_in[8];
    const float* b2     = (const float*)d_in[9];
    float* out = (float*)d_out;

    int E = in_sizes[1] / 2;
    int tot = E + N_NODES;

    float *p_h1, *p_act1, *p_h2;
    int* p_deg;
    cudaGetSymbolAddress((void**)&p_h1,   g_h1);
    cudaGetSymbolAddress((void**)&p_act1, g_act1);
    cudaGetSymbolAddress((void**)&p_h2,   g_h2);
    cudaGetSymbolAddress((void**)&p_deg,  g_deg);

    // CSR build
    cudaMemsetAsync(p_deg, 0, N_NODES * sizeof(int));
    k_count<<<(tot + 255) / 256, 256>>>(ei, E);
    k_scan<<<1, 1024>>>();
    k_scatter<<<(tot + 255) / 256, 256>>>(ei, E);

    // Layer 1
    k_mma_gemm<128, 64><<<dim3(HC1 / 128, (N_NODES + 127) / 128), 256>>>(
        N_NODES, HC1, F_IN, x, W1, p_h1);
    k_score1<<<N_NODES, 256>>>(a_src1, a_dst1);
    k_agg1<<<N_NODES, 128>>>(b1);

    // Layer 2
    k_mma_gemm<64, 32><<<dim3(C2 / 128, (N_NODES + 63) / 64), 256>>>(
        N_NODES, C2, HC1, p_act1, W2, p_h2);
    k_score2<<<(N_NODES + 7) / 8, 256>>>(a_src2, a_dst2);
    k_agg2<<<N_NODES, 128>>>(b2, out);
}

// round 6
// speedup vs baseline: 2.2661x; 1.2758x over previous
#include <cuda_runtime.h>
#include <cuda_fp16.h>
#include <cstdint>

// ---------------------------------------------------------------------------
// GAT 2-layer forward, GB300 (sm_103a)
//   cvt(x,W) -> CSR build -> fp16 MMA GEMM1 (fp16 out) -> score1 ->
//   agg1(online softmax, fp16 gather, ELU, fp16 out) -> fp16 GEMM2 (fp32 out)
//   -> score2 -> agg2 -> out
// ---------------------------------------------------------------------------

#define N_NODES 10000
#define F_IN    256
#define H1      8
#define C1      128
#define HC1     1024
#define C2      128
#define E_BASE  160000
#define E_TOT   (E_BASE + N_NODES)
#define SLOPE   0.2f

__device__ __half g_xh[N_NODES * F_IN];    // x in fp16
__device__ __half g_w1t[HC1 * F_IN];       // W1^T fp16  [1024][256]
__device__ __half g_w2t[C2 * HC1];         // W2^T fp16  [128][1024]
__device__ __half g_h1h[N_NODES * HC1];    // layer-1 features (fp16)
__device__ __half g_act1h[N_NODES * HC1];  // elu(agg1+b1) fp16
__device__ float  g_h2[N_NODES * C2];      // layer-2 features (fp32)
__device__ float  g_s1s[N_NODES * H1];
__device__ float  g_s1d[N_NODES * H1];
__device__ float  g_s2s[N_NODES];
__device__ float  g_s2d[N_NODES];
__device__ int    g_deg[N_NODES];
__device__ int    g_rows[N_NODES + 1];
__device__ int    g_cur[N_NODES];
__device__ int    g_csr[E_TOT + 16];

// ---------------------------------------------------------------------------
// converts / transposes (one-time, tiny)
// ---------------------------------------------------------------------------
__global__ void k_cvt_x(const float* __restrict__ x) {
    int i = blockIdx.x * blockDim.x + threadIdx.x;
    int tot = N_NODES * F_IN / 4;
    if (i >= tot) return;
    float4 v = ((const float4*)x)[i];
    __half2 p0 = __floats2half2_rn(v.x, v.y);
    __half2 p1 = __floats2half2_rn(v.z, v.w);
    uint2 u;
    u.x = *(uint32_t*)&p0;
    u.y = *(uint32_t*)&p1;
    ((uint2*)g_xh)[i] = u;
}

// W [K][N] fp32 -> Wt [N][K] fp16.  K, N multiples of 32.
__global__ void k_tr_cvt(const float* __restrict__ W, __half* __restrict__ Wt,
                         int K, int N) {
    __shared__ float t[32][33];
    int bx = blockIdx.x * 32;  // n
    int by = blockIdx.y * 32;  // k
#pragma unroll
    for (int i = 0; i < 4; i++) {
        int row = threadIdx.y + i * 8;
        t[row][threadIdx.x] = W[(size_t)(by + row) * N + bx + threadIdx.x];
    }
    __syncthreads();
#pragma unroll
    for (int i = 0; i < 4; i++) {
        int row = threadIdx.y + i * 8;
        Wt[(size_t)(bx + row) * K + by + threadIdx.x] =
            __float2half_rn(t[threadIdx.x][row]);
    }
}

// ---------------------------------------------------------------------------
// CSR build
// ---------------------------------------------------------------------------
__global__ void k_count(const int* __restrict__ ei, int E) {
    int i = blockIdx.x * blockDim.x + threadIdx.x;
    int tot = E + N_NODES;
    if (i >= tot) return;
    int dst = (i < E) ? ei[E + i] : (i - E);
    atomicAdd(&g_deg[dst], 1);
}

__global__ void k_scan() {
    __shared__ int ssum[1024];
    int tid = threadIdx.x;
    const int CH = (N_NODES + 1023) >> 10;
    int base = tid * CH;
    int s = 0;
    for (int i = 0; i < CH; i++) {
        int idx = base + i;
        if (idx < N_NODES) s += g_deg[idx];
    }
    ssum[tid] = s;
    __syncthreads();
    for (int off = 1; off < 1024; off <<= 1) {
        int v = (tid >= off) ? ssum[tid - off] : 0;
        __syncthreads();
        ssum[tid] += v;
        __syncthreads();
    }
    int run = (tid == 0) ? 0 : ssum[tid - 1];
    for (int i = 0; i < CH; i++) {
        int idx = base + i;
        if (idx < N_NODES) {
            g_rows[idx] = run;
            g_cur[idx]  = run;
            run += g_deg[idx];
        }
    }
    if (tid == 1023) g_rows[N_NODES] = ssum[1023];
}

__global__ void k_scatter(const int* __restrict__ ei, int E) {
    int i = blockIdx.x * blockDim.x + threadIdx.x;
    int tot = E + N_NODES;
    if (i >= tot) return;
    int src = (i < E) ? ei[i]     : (i - E);
    int dst = (i < E) ? ei[E + i] : (i - E);
    int p = atomicAdd(&g_cur[dst], 1);
    g_csr[p] = src;
}

// ---------------------------------------------------------------------------
// fp16 tensor-core GEMM: C[M,N] = A[M,K] @ Bt[N,K]^T
// A fp16 K-contig, Bt fp16 K-contig; fp32 accumulate.
// BN=128, BK=32, 8 warps (BM/WM=2 m-warps x 4 n-warps).
// Smem stride 40 halves -> all fragment LDS conflict-free.
// HOUT: write fp16 (half2), else fp32 (float2).
// ---------------------------------------------------------------------------
__device__ __forceinline__ void mma_f16(float* c, const uint32_t* a, const uint32_t* b) {
    asm volatile(
        "mma.sync.aligned.m16n8k16.row.col.f32.f16.f16.f32 "
        "{%0,%1,%2,%3}, {%4,%5,%6,%7}, {%8,%9}, {%0,%1,%2,%3};"
        : "+f"(c[0]), "+f"(c[1]), "+f"(c[2]), "+f"(c[3])
        : "r"(a[0]), "r"(a[1]), "r"(a[2]), "r"(a[3]), "r"(b[0]), "r"(b[1]));
}

template<int BM, int WM, bool HOUT>
__global__ __launch_bounds__(256)
void k_hgemm(int M, int N, int K,
             const __half* __restrict__ A, const __half* __restrict__ Bt,
             float* __restrict__ Cf, __half* __restrict__ Ch) {
    constexpr int BN = 128, BK = 32;
    constexpr int SA = BK + 8;           // 40 halves
    constexpr int MT = WM / 16;
    constexpr int AR = BM / 64;          // uint4 A-load rounds

    __shared__ __align__(16) __half As[2][BM * SA];
    __shared__ __align__(16) __half Bs[2][BN * SA];

    int tid = threadIdx.x, wid = tid >> 5, lane = tid & 31;
    int bm0 = blockIdx.y * BM, bn0 = blockIdx.x * BN;
    int wm = (wid >> 2) * WM, wn = (wid & 3) * 32;

    float acc[MT][4][4];
#pragma unroll
    for (int i = 0; i < MT; i++)
#pragma unroll
        for (int j = 0; j < 4; j++)
#pragma unroll
            for (int l = 0; l < 4; l++) acc[i][j][l] = 0.f;

    int ld_row = tid >> 2;               // 0..63
    int ld_ch  = (tid & 3) * 8;          // half-offset within BK

    uint4 ga[AR], gb[2];

    auto ldg = [&](int k0) {
#pragma unroll
        for (int i = 0; i < AR; i++) {
            int r = bm0 + ld_row + i * 64;
            ga[i] = (r < M) ? *(const uint4*)(A + (size_t)r * K + k0 + ld_ch)
                            : make_uint4(0u, 0u, 0u, 0u);
        }
#pragma unroll
        for (int i = 0; i < 2; i++) {
            int n = bn0 + ld_row + i * 64;
            gb[i] = *(const uint4*)(Bt + (size_t)n * K + k0 + ld_ch);
        }
    };
    auto sts = [&](int buf) {
#pragma unroll
        for (int i = 0; i < AR; i++)
            *(uint4*)&As[buf][(ld_row + i * 64) * SA + ld_ch] = ga[i];
#pragma unroll
        for (int i = 0; i < 2; i++)
            *(uint4*)&Bs[buf][(ld_row + i * 64) * SA + ld_ch] = gb[i];
    };
    auto compute = [&](int buf) {
#pragma unroll
        for (int ks = 0; ks < 2; ks++) {
            int k = ks * 16;
            int kp = k + (lane & 3) * 2;
            uint32_t af[MT][4], bf[4][2];
#pragma unroll
            for (int mt = 0; mt < MT; mt++) {
                int r = wm + mt * 16 + (lane >> 2);
                af[mt][0] = *(const uint32_t*)&As[buf][r * SA + kp];
                af[mt][1] = *(const uint32_t*)&As[buf][(r + 8) * SA + kp];
                af[mt][2] = *(const uint32_t*)&As[buf][r * SA + kp + 8];
                af[mt][3] = *(const uint32_t*)&As[buf][(r + 8) * SA + kp + 8];
            }
#pragma unroll
            for (int nt = 0; nt < 4; nt++) {
                int n = wn + nt * 8 + (lane >> 2);
                bf[nt][0] = *(const uint32_t*)&Bs[buf][n * SA + kp];
                bf[nt][1] = *(const uint32_t*)&Bs[buf][n * SA + kp + 8];
            }
#pragma unroll
            for (int mt = 0; mt < MT; mt++)
#pragma unroll
                for (int nt = 0; nt < 4; nt++)
                    mma_f16(acc[mt][nt], af[mt], bf[nt]);
        }
    };

    ldg(0);
    sts(0);
    __syncthreads();
    int iters = K / BK;
    for (int it = 0; it < iters; it++) {
        int cur = it & 1;
        if (it + 1 < iters) ldg((it + 1) * BK);
        compute(cur);
        if (it + 1 < iters) {
            sts(cur ^ 1);
            __syncthreads();
        }
    }

#pragma unroll
    for (int mt = 0; mt < MT; mt++) {
        int r = bm0 + wm + mt * 16 + (lane >> 2);
#pragma unroll
        for (int nt = 0; nt < 4; nt++) {
            int c = bn0 + wn + nt * 8 + (lane & 3) * 2;
            if (HOUT) {
                if (r < M) {
                    __half2 h = __floats2half2_rn(acc[mt][nt][0], acc[mt][nt][1]);
                    *(__half2*)(Ch + (size_t)r * N + c) = h;
                }
                if (r + 8 < M) {
                    __half2 h = __floats2half2_rn(acc[mt][nt][2], acc[mt][nt][3]);
                    *(__half2*)(Ch + (size_t)(r + 8) * N + c) = h;
                }
            } else {
                if (r < M)
                    *(float2*)(Cf + (size_t)r * N + c) =
                        make_float2(acc[mt][nt][0], acc[mt][nt][1]);
                if (r + 8 < M)
                    *(float2*)(Cf + (size_t)(r + 8) * N + c) =
                        make_float2(acc[mt][nt][2], acc[mt][nt][3]);
            }
        }
    }
}

// ---------------------------------------------------------------------------
// score1: reads fp16 h1; per node/head dot products
// ---------------------------------------------------------------------------
__global__ __launch_bounds__(256)
void k_score1(const float* __restrict__ a_src, const float* __restrict__ a_dst) {
    int node = blockIdx.x;
    int wid = threadIdx.x >> 5, lane = threadIdx.x & 31;
    size_t off = (size_t)node * HC1 + wid * C1 + lane * 4;
    uint2 u = *(const uint2*)(g_h1h + off);
    float2 v0 = __half22float2(*(__half2*)&u.x);
    float2 v1 = __half22float2(*(__half2*)&u.y);

    float4 as = *(const float4*)(a_src + wid * C1 + lane * 4);
    float4 ad = *(const float4*)(a_dst + wid * C1 + lane * 4);
    float s1 = v0.x * as.x + v0.y * as.y + v1.x * as.z + v1.y * as.w;
    float s2 = v0.x * ad.x + v0.y * ad.y + v1.x * ad.z + v1.y * ad.w;
#pragma unroll
    for (int o = 16; o; o >>= 1) {
        s1 += __shfl_xor_sync(~0u, s1, o);
        s2 += __shfl_xor_sync(~0u, s2, o);
    }
    if (!lane) {
        g_s1s[node * H1 + wid] = s1;
        g_s1d[node * H1 + wid] = s2;
    }
}

// ---------------------------------------------------------------------------
// agg1: one block (128 thr) per dst node; online softmax; fp16 gather;
// writes fp16 act1 (+b1, ELU).
// ---------------------------------------------------------------------------
__global__ __launch_bounds__(128)
void k_agg1(const float* __restrict__ b1) {
    int n = blockIdx.x;
    int tid = threadIdx.x, wid = tid >> 5, lane = tid & 31;
    __shared__ float  sdl[8], smax[8], sden[8];
    __shared__ float2 wr[4][8];
    __shared__ float  sal[16][8];
    __shared__ int    ssrc[16];

    if (tid < 8) sdl[tid] = g_s1d[n * H1 + tid];
    int r0 = g_rows[n], r1 = g_rows[n + 1];
    int deg = r1 - r0;
    __syncthreads();

    int myh = tid & 7;
    float sdh = sdl[myh];

    float m = -3.0e38f, s = 0.f;
    for (int idx = tid; idx < deg * 8; idx += 128) {
        int src = g_csr[r0 + (idx >> 3)];
        float v = g_s1s[src * H1 + myh] + sdh;
        v = v > 0.f ? v : SLOPE * v;
        float nm = fmaxf(m, v);
        s = s * __expf(m - nm) + __expf(v - nm);
        m = nm;
    }
#pragma unroll
    for (int o = 8; o <= 16; o <<= 1) {
        float om = __shfl_xor_sync(~0u, m, o);
        float os = __shfl_xor_sync(~0u, s, o);
        float nm = fmaxf(m, om);
        s = s * __expf(m - nm) + os * __expf(om - nm);
        m = nm;
    }
    if (lane < 8) wr[wid][lane] = make_float2(m, s);
    __syncthreads();
    if (tid < 8) {
        float M = wr[0][tid].x, S = wr[0][tid].y;
#pragma unroll
        for (int w = 1; w < 4; w++) {
            float m2 = wr[w][tid].x, s2 = wr[w][tid].y;
            float nm = fmaxf(M, m2);
            S = S * __expf(M - nm) + s2 * __expf(m2 - nm);
            M = nm;
        }
        smax[tid] = M;
        sden[tid] = 1.f / S;
    }
    __syncthreads();

    float acc[8];
#pragma unroll
    for (int k = 0; k < 8; k++) acc[k] = 0.f;
    int c0 = tid * 8;
    int hown = tid >> 4;

    for (int e0 = r0; e0 < r1; e0 += 16) {
        int mc = min(16, r1 - e0);
        if (tid < mc * 8) {
            int e = e0 + (tid >> 3);
            int h = tid & 7;
            int src = g_csr[e];
            if (h == 0) ssrc[tid >> 3] = src;
            float v = g_s1s[src * H1 + h] + sdl[h];
            v = v > 0.f ? v : SLOPE * v;
            sal[tid >> 3][h] = __expf(v - smax[h]) * sden[h];
        }
        __syncthreads();
        for (int j = 0; j < mc; j++) {
            int src = ssrc[j];
            float a = sal[j][hown];
            uint4 u = *(const uint4*)(g_h1h + (size_t)src * HC1 + c0);
            float2 f0 = __half22float2(*(__half2*)&u.x);
            float2 f1 = __half22float2(*(__half2*)&u.y);
            float2 f2 = __half22float2(*(__half2*)&u.z);
            float2 f3 = __half22float2(*(__half2*)&u.w);
            acc[0] = fmaf(f0.x, a, acc[0]); acc[1] = fmaf(f0.y, a, acc[1]);
            acc[2] = fmaf(f1.x, a, acc[2]); acc[3] = fmaf(f1.y, a, acc[3]);
            acc[4] = fmaf(f2.x, a, acc[4]); acc[5] = fmaf(f2.y, a, acc[5]);
            acc[6] = fmaf(f3.x, a, acc[6]); acc[7] = fmaf(f3.y, a, acc[7]);
        }
        __syncthreads();
    }

    float o[8];
#pragma unroll
    for (int k = 0; k < 8; k++) {
        float t = acc[k] + b1[c0 + k];
        o[k] = t > 0.f ? t : expm1f(t);
    }
    __half2 h0 = __floats2half2_rn(o[0], o[1]);
    __half2 h1v = __floats2half2_rn(o[2], o[3]);
    __half2 h2v = __floats2half2_rn(o[4], o[5]);
    __half2 h3 = __floats2half2_rn(o[6], o[7]);
    uint4 u;
    u.x = *(uint32_t*)&h0;
    u.y = *(uint32_t*)&h1v;
    u.z = *(uint32_t*)&h2v;
    u.w = *(uint32_t*)&h3;
    *(uint4*)(g_act1h + (size_t)n * HC1 + c0) = u;
}

// ---------------------------------------------------------------------------
// score2
// ---------------------------------------------------------------------------
__global__ __launch_bounds__(256)
void k_score2(const float* __restrict__ a_src, const float* __restrict__ a_dst) {
    int node = blockIdx.x * 8 + (threadIdx.x >> 5);
    int lane = threadIdx.x & 31;
    if (node >= N_NODES) return;
    const float* hr = g_h2 + (size_t)node * C2;
    float4 v = *(const float4*)(hr + lane * 4);
    float4 as = *(const float4*)(a_src + lane * 4);
    float4 ad = *(const float4*)(a_dst + lane * 4);
    float s1 = v.x * as.x + v.y * as.y + v.z * as.z + v.w * as.w;
    float s2 = v.x * ad.x + v.y * ad.y + v.z * ad.z + v.w * ad.w;
#pragma unroll
    for (int o = 16; o; o >>= 1) {
        s1 += __shfl_xor_sync(~0u, s1, o);
        s2 += __shfl_xor_sync(~0u, s2, o);
    }
    if (!lane) {
        g_s2s[node] = s1;
        g_s2d[node] = s2;
    }
}

// ---------------------------------------------------------------------------
// agg2: fp32 gather; writes final output
// ---------------------------------------------------------------------------
__global__ __launch_bounds__(128)
void k_agg2(const float* __restrict__ b2, float* __restrict__ out) {
    int n = blockIdx.x;
    int tid = threadIdx.x, wid = tid >> 5, lane = tid & 31;
    __shared__ float s_sd, s_m, s_d;
    __shared__ float2 wr[4];
    __shared__ float sal[64];
    __shared__ int   ssrc[64];

    if (tid == 0) s_sd = g_s2d[n];
    int r0 = g_rows[n], r1 = g_rows[n + 1];
    int deg = r1 - r0;
    __syncthreads();
    float sdv = s_sd;

    float m = -3.0e38f, s = 0.f;
    for (int i = tid; i < deg; i += 128) {
        int src = g_csr[r0 + i];
        float v = g_s2s[src] + sdv;
        v = v > 0.f ? v : SLOPE * v;
        float nm = fmaxf(m, v);
        s = s * __expf(m - nm) + __expf(v - nm);
        m = nm;
    }
#pragma unroll
    for (int o = 16; o; o >>= 1) {
        float om = __shfl_xor_sync(~0u, m, o);
        float os = __shfl_xor_sync(~0u, s, o);
        float nm = fmaxf(m, om);
        s = s * __expf(m - nm) + os * __expf(om - nm);
        m = nm;
    }
    if (!lane) wr[wid] = make_float2(m, s);
    __syncthreads();
    if (tid == 0) {
        float M = wr[0].x, S = wr[0].y;
#pragma unroll
        for (int w = 1; w < 4; w++) {
            float m2 = wr[w].x, s2 = wr[w].y;
            float nm = fmaxf(M, m2);
            S = S * __expf(M - nm) + s2 * __expf(m2 - nm);
            M = nm;
        }
        s_m = M;
        s_d = 1.f / S;
    }
    __syncthreads();
    float M = s_m, inv = s_d;

    float acc = 0.f;
    for (int e0 = r0; e0 < r1; e0 += 64) {
        int mc = min(64, r1 - e0);
        if (tid < mc) {
            int src = g_csr[e0 + tid];
            float v = g_s2s[src] + sdv;
            v = v > 0.f ? v : SLOPE * v;
            sal[tid] = __expf(v - M) * inv;
            ssrc[tid] = src;
        }
        __syncthreads();
        for (int j = 0; j < mc; j++)
            acc = fmaf(g_h2[(size_t)ssrc[j] * C2 + tid], sal[j], acc);
        __syncthreads();
    }
    out[(size_t)n * C2 + tid] = acc + b2[tid];
}

// ---------------------------------------------------------------------------
// launch
// ---------------------------------------------------------------------------
extern "C" void kernel_launch(void* const* d_in, const int* in_sizes, int n_in,
                              void* d_out, int out_size) {
    const float* x      = (const float*)d_in[0];
    const int*   ei     = (const int*)  d_in[1];
    const float* W1     = (const float*)d_in[2];
    const float* a_src1 = (const float*)d_in[3];
    const float* a_dst1 = (const float*)d_in[4];
    const float* b1     = (const float*)d_in[5];
    const float* W2     = (const float*)d_in[6];
    const float* a_src2 = (const float*)d_in[7];
    const float* a_dst2 = (const float*)d_in[8];
    const float* b2     = (const float*)d_in[9];
    float* out = (float*)d_out;

    int E = in_sizes[1] / 2;
    int tot = E + N_NODES;

    __half *p_xh, *p_w1t, *p_w2t, *p_h1h, *p_act1h;
    float *p_h2;
    int* p_deg;
    cudaGetSymbolAddress((void**)&p_xh,    g_xh);
    cudaGetSymbolAddress((void**)&p_w1t,   g_w1t);
    cudaGetSymbolAddress((void**)&p_w2t,   g_w2t);
    cudaGetSymbolAddress((void**)&p_h1h,   g_h1h);
    cudaGetSymbolAddress((void**)&p_act1h, g_act1h);
    cudaGetSymbolAddress((void**)&p_h2,    g_h2);
    cudaGetSymbolAddress((void**)&p_deg,   g_deg);

    // converts (independent of CSR)
    k_cvt_x<<<(N_NODES * F_IN / 4 + 255) / 256, 256>>>(x);
    k_tr_cvt<<<dim3(HC1 / 32, F_IN / 32), dim3(32, 8)>>>(W1, p_w1t, F_IN, HC1);
    k_tr_cvt<<<dim3(C2 / 32, HC1 / 32), dim3(32, 8)>>>(W2, p_w2t, HC1, C2);

    // CSR build
    cudaMemsetAsync(p_deg, 0, N_NODES * sizeof(int));
    k_count<<<(tot + 255) / 256, 256>>>(ei, E);
    k_scan<<<1, 1024>>>();
    k_scatter<<<(tot + 255) / 256, 256>>>(ei, E);

    // Layer 1: fp16 MMA GEMM -> fp16 h1
    k_hgemm<128, 64, true><<<dim3(HC1 / 128, (N_NODES + 127) / 128), 256>>>(
        N_NODES, HC1, F_IN, p_xh, p_w1t, nullptr, p_h1h);
    k_score1<<<N_NODES, 256>>>(a_src1, a_dst1);
    k_agg1<<<N_NODES, 128>>>(b1);

    // Layer 2: fp16 MMA GEMM -> fp32 h2
    k_hgemm<64, 32, false><<<dim3(C2 / 128, (N_NODES + 63) / 64), 256>>>(
        N_NODES, C2, HC1, p_act1h, p_w2t, p_h2, nullptr);
    k_score2<<<(N_NODES + 7) / 8, 256>>>(a_src2, a_dst2);
    k_agg2<<<N_NODES, 128>>>(b2, out);
}

// round 7
// speedup vs baseline: 2.3796x; 1.0501x over previous
#include <cuda_runtime.h>
#include <cuda_fp16.h>
#include <cstdint>

// ---------------------------------------------------------------------------
// GAT 2-layer forward, GB300 (sm_103a)
//   cvt(x,W) -> CSR build -> fp16 GEMM1 (+fused score1, fp16 out) ->
//   agg1(online softmax, fp16 gather, ELU, fp16 out) ->
//   fp16 GEMM2 (+fused score2, fp16 out) -> agg2 -> out
// ---------------------------------------------------------------------------

#define N_NODES 10000
#define F_IN    256
#define H1      8
#define C1      128
#define HC1     1024
#define C2      128
#define E_BASE  160000
#define E_TOT   (E_BASE + N_NODES)
#define SLOPE   0.2f

__device__ __half g_xh[N_NODES * F_IN];    // x in fp16
__device__ __half g_w1t[HC1 * F_IN];       // W1^T fp16  [1024][256]
__device__ __half g_w2t[C2 * HC1];         // W2^T fp16  [128][1024]
__device__ __half g_h1h[N_NODES * HC1];    // layer-1 features (fp16)
__device__ __half g_act1h[N_NODES * HC1];  // elu(agg1+b1) fp16
__device__ __half g_h2h[N_NODES * C2];     // layer-2 features (fp16)
__device__ float  g_s1s[N_NODES * H1];
__device__ float  g_s1d[N_NODES * H1];
__device__ float  g_s2s[N_NODES];
__device__ float  g_s2d[N_NODES];
__device__ int    g_deg[N_NODES];
__device__ int    g_rows[N_NODES + 1];
__device__ int    g_cur[N_NODES];
__device__ int    g_csr[E_TOT + 16];

// ---------------------------------------------------------------------------
// converts / transposes (one-time, tiny)
// ---------------------------------------------------------------------------
__global__ void k_cvt_x(const float* __restrict__ x) {
    int i = blockIdx.x * blockDim.x + threadIdx.x;
    int tot = N_NODES * F_IN / 4;
    if (i >= tot) return;
    float4 v = ((const float4*)x)[i];
    __half2 p0 = __floats2half2_rn(v.x, v.y);
    __half2 p1 = __floats2half2_rn(v.z, v.w);
    uint2 u;
    u.x = *(uint32_t*)&p0;
    u.y = *(uint32_t*)&p1;
    ((uint2*)g_xh)[i] = u;
}

// W [K][N] fp32 -> Wt [N][K] fp16.
__global__ void k_tr_cvt(const float* __restrict__ W, __half* __restrict__ Wt,
                         int K, int N) {
    __shared__ float t[32][33];
    int bx = blockIdx.x * 32;  // n
    int by = blockIdx.y * 32;  // k
#pragma unroll
    for (int i = 0; i < 4; i++) {
        int row = threadIdx.y + i * 8;
        t[row][threadIdx.x] = W[(size_t)(by + row) * N + bx + threadIdx.x];
    }
    __syncthreads();
#pragma unroll
    for (int i = 0; i < 4; i++) {
        int row = threadIdx.y + i * 8;
        Wt[(size_t)(bx + row) * K + by + threadIdx.x] =
            __float2half_rn(t[threadIdx.x][row]);
    }
}

// ---------------------------------------------------------------------------
// CSR build
// ---------------------------------------------------------------------------
__global__ void k_count(const int* __restrict__ ei, int E) {
    int i = blockIdx.x * blockDim.x + threadIdx.x;
    int tot = E + N_NODES;
    if (i >= tot) return;
    int dst = (i < E) ? ei[E + i] : (i - E);
    atomicAdd(&g_deg[dst], 1);
}

__global__ void k_scan() {
    __shared__ int ssum[1024];
    int tid = threadIdx.x;
    const int CH = (N_NODES + 1023) >> 10;
    int base = tid * CH;
    int s = 0;
    for (int i = 0; i < CH; i++) {
        int idx = base + i;
        if (idx < N_NODES) s += g_deg[idx];
    }
    ssum[tid] = s;
    __syncthreads();
    for (int off = 1; off < 1024; off <<= 1) {
        int v = (tid >= off) ? ssum[tid - off] : 0;
        __syncthreads();
        ssum[tid] += v;
        __syncthreads();
    }
    int run = (tid == 0) ? 0 : ssum[tid - 1];
    for (int i = 0; i < CH; i++) {
        int idx = base + i;
        if (idx < N_NODES) {
            g_rows[idx] = run;
            g_cur[idx]  = run;
            run += g_deg[idx];
        }
    }
    if (tid == 1023) g_rows[N_NODES] = ssum[1023];
}

__global__ void k_scatter(const int* __restrict__ ei, int E) {
    int i = blockIdx.x * blockDim.x + threadIdx.x;
    int tot = E + N_NODES;
    if (i >= tot) return;
    int src = (i < E) ? ei[i]     : (i - E);
    int dst = (i < E) ? ei[E + i] : (i - E);
    int p = atomicAdd(&g_cur[dst], 1);
    g_csr[p] = src;
}

// ---------------------------------------------------------------------------
// fp16 tensor-core GEMM + fused attention-score epilogue.
// C[M,N] = A[M,K] @ Bt[N,K]^T  (fp16 in, fp32 accum, fp16 out)
// BN=128 == one head's channels -> each block computes its rows' COMPLETE
// s_src/s_dst for head = blockIdx.x; reduced via quad-shuffle + 4KB smem.
// ss/sd layout: [row*HS + head].
// ---------------------------------------------------------------------------
__device__ __forceinline__ void mma_f16(float* c, const uint32_t* a, const uint32_t* b) {
    asm volatile(
        "mma.sync.aligned.m16n8k16.row.col.f32.f16.f16.f32 "
        "{%0,%1,%2,%3}, {%4,%5,%6,%7}, {%8,%9}, {%0,%1,%2,%3};"
        : "+f"(c[0]), "+f"(c[1]), "+f"(c[2]), "+f"(c[3])
        : "r"(a[0]), "r"(a[1]), "r"(a[2]), "r"(a[3]), "r"(b[0]), "r"(b[1]));
}

template<int BM, int WM>
__global__ __launch_bounds__(256)
void k_hgemm(int M, int N, int K,
             const __half* __restrict__ A, const __half* __restrict__ Bt,
             __half* __restrict__ Ch,
             float* __restrict__ ss, float* __restrict__ sd,
             const float* __restrict__ a_src, const float* __restrict__ a_dst,
             int HS) {
    constexpr int BN = 128, BK = 32;
    constexpr int SA = BK + 8;           // 40 halves
    constexpr int MT = WM / 16;
    constexpr int AR = BM / 64;

    __shared__ __align__(16) __half As[2][BM * SA];
    __shared__ __align__(16) __half Bs[2][BN * SA];
    __shared__ float s_red[BM][4][2];

    int tid = threadIdx.x, wid = tid >> 5, lane = tid & 31;
    int bm0 = blockIdx.y * BM, bn0 = blockIdx.x * BN;
    int wm = (wid >> 2) * WM, wn = (wid & 3) * 32;

    float acc[MT][4][4];
#pragma unroll
    for (int i = 0; i < MT; i++)
#pragma unroll
        for (int j = 0; j < 4; j++)
#pragma unroll
            for (int l = 0; l < 4; l++) acc[i][j][l] = 0.f;

    int ld_row = tid >> 2;
    int ld_ch  = (tid & 3) * 8;

    uint4 ga[AR], gb[2];

    auto ldg = [&](int k0) {
#pragma unroll
        for (int i = 0; i < AR; i++) {
            int r = bm0 + ld_row + i * 64;
            ga[i] = (r < M) ? *(const uint4*)(A + (size_t)r * K + k0 + ld_ch)
                            : make_uint4(0u, 0u, 0u, 0u);
        }
#pragma unroll
        for (int i = 0; i < 2; i++) {
            int n = bn0 + ld_row + i * 64;
            gb[i] = *(const uint4*)(Bt + (size_t)n * K + k0 + ld_ch);
        }
    };
    auto sts = [&](int buf) {
#pragma unroll
        for (int i = 0; i < AR; i++)
            *(uint4*)&As[buf][(ld_row + i * 64) * SA + ld_ch] = ga[i];
#pragma unroll
        for (int i = 0; i < 2; i++)
            *(uint4*)&Bs[buf][(ld_row + i * 64) * SA + ld_ch] = gb[i];
    };
    auto compute = [&](int buf) {
#pragma unroll
        for (int ks = 0; ks < 2; ks++) {
            int k = ks * 16;
            int kp = k + (lane & 3) * 2;
            uint32_t af[MT][4], bf[4][2];
#pragma unroll
            for (int mt = 0; mt < MT; mt++) {
                int r = wm + mt * 16 + (lane >> 2);
                af[mt][0] = *(const uint32_t*)&As[buf][r * SA + kp];
                af[mt][1] = *(const uint32_t*)&As[buf][(r + 8) * SA + kp];
                af[mt][2] = *(const uint32_t*)&As[buf][r * SA + kp + 8];
                af[mt][3] = *(const uint32_t*)&As[buf][(r + 8) * SA + kp + 8];
            }
#pragma unroll
            for (int nt = 0; nt < 4; nt++) {
                int n = wn + nt * 8 + (lane >> 2);
                bf[nt][0] = *(const uint32_t*)&Bs[buf][n * SA + kp];
                bf[nt][1] = *(const uint32_t*)&Bs[buf][n * SA + kp + 8];
            }
#pragma unroll
            for (int mt = 0; mt < MT; mt++)
#pragma unroll
                for (int nt = 0; nt < 4; nt++)
                    mma_f16(acc[mt][nt], af[mt], bf[nt]);
        }
    };

    ldg(0);
    sts(0);
    __syncthreads();
    int iters = K / BK;
    for (int it = 0; it < iters; it++) {
        int cur = it & 1;
        if (it + 1 < iters) ldg((it + 1) * BK);
        compute(cur);
        if (it + 1 < iters) {
            sts(cur ^ 1);
            __syncthreads();
        }
    }

    // ---- C store (fp16) + fused score partials ----
    float ps[MT][2], pd[MT][2];
#pragma unroll
    for (int mt = 0; mt < MT; mt++) {
        ps[mt][0] = ps[mt][1] = 0.f;
        pd[mt][0] = pd[mt][1] = 0.f;
    }
#pragma unroll
    for (int nt = 0; nt < 4; nt++) {
        int cl = wn + nt * 8 + (lane & 3) * 2;     // column within head
        float a0s = a_src[bn0 + cl], a1s = a_src[bn0 + cl + 1];
        float a0d = a_dst[bn0 + cl], a1d = a_dst[bn0 + cl + 1];
#pragma unroll
        for (int mt = 0; mt < MT; mt++) {
            int r = bm0 + wm + mt * 16 + (lane >> 2);
            int c = bn0 + cl;
            if (r < M) {
                __half2 h = __floats2half2_rn(acc[mt][nt][0], acc[mt][nt][1]);
                *(__half2*)(Ch + (size_t)r * N + c) = h;
            }
            if (r + 8 < M) {
                __half2 h = __floats2half2_rn(acc[mt][nt][2], acc[mt][nt][3]);
                *(__half2*)(Ch + (size_t)(r + 8) * N + c) = h;
            }
            ps[mt][0] = fmaf(acc[mt][nt][0], a0s, fmaf(acc[mt][nt][1], a1s, ps[mt][0]));
            ps[mt][1] = fmaf(acc[mt][nt][2], a0s, fmaf(acc[mt][nt][3], a1s, ps[mt][1]));
            pd[mt][0] = fmaf(acc[mt][nt][0], a0d, fmaf(acc[mt][nt][1], a1d, pd[mt][0]));
            pd[mt][1] = fmaf(acc[mt][nt][2], a0d, fmaf(acc[mt][nt][3], a1d, pd[mt][1]));
        }
    }
    // reduce over the 4 quad-lanes (lane&3)
#pragma unroll
    for (int o = 1; o <= 2; o <<= 1) {
#pragma unroll
        for (int mt = 0; mt < MT; mt++) {
            ps[mt][0] += __shfl_xor_sync(~0u, ps[mt][0], o);
            ps[mt][1] += __shfl_xor_sync(~0u, ps[mt][1], o);
            pd[mt][0] += __shfl_xor_sync(~0u, pd[mt][0], o);
            pd[mt][1] += __shfl_xor_sync(~0u, pd[mt][1], o);
        }
    }
    if ((lane & 3) == 0) {
        int nw = wid & 3;
#pragma unroll
        for (int mt = 0; mt < MT; mt++) {
            int row = wm + mt * 16 + (lane >> 2);
            s_red[row][nw][0] = ps[mt][0];
            s_red[row][nw][1] = pd[mt][0];
            s_red[row + 8][nw][0] = ps[mt][1];
            s_red[row + 8][nw][1] = pd[mt][1];
        }
    }
    __syncthreads();
    if (tid < BM) {
        int r = bm0 + tid;
        if (r < M) {
            float s = s_red[tid][0][0] + s_red[tid][1][0] + s_red[tid][2][0] + s_red[tid][3][0];
            float d = s_red[tid][0][1] + s_red[tid][1][1] + s_red[tid][2][1] + s_red[tid][3][1];
            ss[(size_t)r * HS + blockIdx.x] = s;
            sd[(size_t)r * HS + blockIdx.x] = d;
        }
    }
}

// ---------------------------------------------------------------------------
// agg1: one block (128 thr) per dst node; online softmax; fp16 gather;
// writes fp16 act1 (+b1, ELU).
// ---------------------------------------------------------------------------
__global__ __launch_bounds__(128)
void k_agg1(const float* __restrict__ b1) {
    int n = blockIdx.x;
    int tid = threadIdx.x, wid = tid >> 5, lane = tid & 31;
    __shared__ float  sdl[8], smax[8], sden[8];
    __shared__ float2 wr[4][8];
    __shared__ float  sal[16][8];
    __shared__ int    ssrc[16];

    if (tid < 8) sdl[tid] = g_s1d[n * H1 + tid];
    int r0 = g_rows[n], r1 = g_rows[n + 1];
    int deg = r1 - r0;
    __syncthreads();

    int myh = tid & 7;
    float sdh = sdl[myh];

    float m = -3.0e38f, s = 0.f;
    for (int idx = tid; idx < deg * 8; idx += 128) {
        int src = g_csr[r0 + (idx >> 3)];
        float v = g_s1s[src * H1 + myh] + sdh;
        v = v > 0.f ? v : SLOPE * v;
        float nm = fmaxf(m, v);
        s = s * __expf(m - nm) + __expf(v - nm);
        m = nm;
    }
#pragma unroll
    for (int o = 8; o <= 16; o <<= 1) {
        float om = __shfl_xor_sync(~0u, m, o);
        float os = __shfl_xor_sync(~0u, s, o);
        float nm = fmaxf(m, om);
        s = s * __expf(m - nm) + os * __expf(om - nm);
        m = nm;
    }
    if (lane < 8) wr[wid][lane] = make_float2(m, s);
    __syncthreads();
    if (tid < 8) {
        float M = wr[0][tid].x, S = wr[0][tid].y;
#pragma unroll
        for (int w = 1; w < 4; w++) {
            float m2 = wr[w][tid].x, s2 = wr[w][tid].y;
            float nm = fmaxf(M, m2);
            S = S * __expf(M - nm) + s2 * __expf(m2 - nm);
            M = nm;
        }
        smax[tid] = M;
        sden[tid] = 1.f / S;
    }
    __syncthreads();

    float acc[8];
#pragma unroll
    for (int k = 0; k < 8; k++) acc[k] = 0.f;
    int c0 = tid * 8;
    int hown = tid >> 4;

    for (int e0 = r0; e0 < r1; e0 += 16) {
        int mc = min(16, r1 - e0);
        if (tid < mc * 8) {
            int e = e0 + (tid >> 3);
            int h = tid & 7;
            int src = g_csr[e];
            if (h == 0) ssrc[tid >> 3] = src;
            float v = g_s1s[src * H1 + h] + sdl[h];
            v = v > 0.f ? v : SLOPE * v;
            sal[tid >> 3][h] = __expf(v - smax[h]) * sden[h];
        }
        __syncthreads();
        for (int j = 0; j < mc; j++) {
            int src = ssrc[j];
            float a = sal[j][hown];
            uint4 u = *(const uint4*)(g_h1h + (size_t)src * HC1 + c0);
            float2 f0 = __half22float2(*(__half2*)&u.x);
            float2 f1 = __half22float2(*(__half2*)&u.y);
            float2 f2 = __half22float2(*(__half2*)&u.z);
            float2 f3 = __half22float2(*(__half2*)&u.w);
            acc[0] = fmaf(f0.x, a, acc[0]); acc[1] = fmaf(f0.y, a, acc[1]);
            acc[2] = fmaf(f1.x, a, acc[2]); acc[3] = fmaf(f1.y, a, acc[3]);
            acc[4] = fmaf(f2.x, a, acc[4]); acc[5] = fmaf(f2.y, a, acc[5]);
            acc[6] = fmaf(f3.x, a, acc[6]); acc[7] = fmaf(f3.y, a, acc[7]);
        }
        __syncthreads();
    }

    float o[8];
#pragma unroll
    for (int k = 0; k < 8; k++) {
        float t = acc[k] + b1[c0 + k];
        o[k] = t > 0.f ? t : expm1f(t);
    }
    __half2 h0 = __floats2half2_rn(o[0], o[1]);
    __half2 h1v = __floats2half2_rn(o[2], o[3]);
    __half2 h2v = __floats2half2_rn(o[4], o[5]);
    __half2 h3 = __floats2half2_rn(o[6], o[7]);
    uint4 u;
    u.x = *(uint32_t*)&h0;
    u.y = *(uint32_t*)&h1v;
    u.z = *(uint32_t*)&h2v;
    u.w = *(uint32_t*)&h3;
    *(uint4*)(g_act1h + (size_t)n * HC1 + c0) = u;
}

// ---------------------------------------------------------------------------
// agg2: fp16 gather; writes final fp32 output
// ---------------------------------------------------------------------------
__global__ __launch_bounds__(128)
void k_agg2(const float* __restrict__ b2, float* __restrict__ out) {
    int n = blockIdx.x;
    int tid = threadIdx.x, wid = tid >> 5, lane = tid & 31;
    __shared__ float s_sd, s_m, s_d;
    __shared__ float2 wr[4];
    __shared__ float sal[64];
    __shared__ int   ssrc[64];

    if (tid == 0) s_sd = g_s2d[n];
    int r0 = g_rows[n], r1 = g_rows[n + 1];
    int deg = r1 - r0;
    __syncthreads();
    float sdv = s_sd;

    float m = -3.0e38f, s = 0.f;
    for (int i = tid; i < deg; i += 128) {
        int src = g_csr[r0 + i];
        float v = g_s2s[src] + sdv;
        v = v > 0.f ? v : SLOPE * v;
        float nm = fmaxf(m, v);
        s = s * __expf(m - nm) + __expf(v - nm);
        m = nm;
    }
#pragma unroll
    for (int o = 16; o; o >>= 1) {
        float om = __shfl_xor_sync(~0u, m, o);
        float os = __shfl_xor_sync(~0u, s, o);
        float nm = fmaxf(m, om);
        s = s * __expf(m - nm) + os * __expf(om - nm);
        m = nm;
    }
    if (!lane) wr[wid] = make_float2(m, s);
    __syncthreads();
    if (tid == 0) {
        float M = wr[0].x, S = wr[0].y;
#pragma unroll
        for (int w = 1; w < 4; w++) {
            float m2 = wr[w].x, s2 = wr[w].y;
            float nm = fmaxf(M, m2);
            S = S * __expf(M - nm) + s2 * __expf(m2 - nm);
            M = nm;
        }
        s_m = M;
        s_d = 1.f / S;
    }
    __syncthreads();
    float M = s_m, inv = s_d;

    float acc = 0.f;
    for (int e0 = r0; e0 < r1; e0 += 64) {
        int mc = min(64, r1 - e0);
        if (tid < mc) {
            int src = g_csr[e0 + tid];
            float v = g_s2s[src] + sdv;
            v = v > 0.f ? v : SLOPE * v;
            sal[tid] = __expf(v - M) * inv;
            ssrc[tid] = src;
        }
        __syncthreads();
        for (int j = 0; j < mc; j++) {
            float hv = __half2float(g_h2h[(size_t)ssrc[j] * C2 + tid]);
            acc = fmaf(hv, sal[j], acc);
        }
        __syncthreads();
    }
    out[(size_t)n * C2 + tid] = acc + b2[tid];
}

// ---------------------------------------------------------------------------
// launch
// ---------------------------------------------------------------------------
extern "C" void kernel_launch(void* const* d_in, const int* in_sizes, int n_in,
                              void* d_out, int out_size) {
    const float* x      = (const float*)d_in[0];
    const int*   ei     = (const int*)  d_in[1];
    const float* W1     = (const float*)d_in[2];
    const float* a_src1 = (const float*)d_in[3];
    const float* a_dst1 = (const float*)d_in[4];
    const float* b1     = (const float*)d_in[5];
    const float* W2     = (const float*)d_in[6];
    const float* a_src2 = (const float*)d_in[7];
    const float* a_dst2 = (const float*)d_in[8];
    const float* b2     = (const float*)d_in[9];
    float* out = (float*)d_out;

    int E = in_sizes[1] / 2;
    int tot = E + N_NODES;

    __half *p_xh, *p_w1t, *p_w2t, *p_h1h, *p_act1h, *p_h2h;
    float *p_s1s, *p_s1d, *p_s2s, *p_s2d;
    int* p_deg;
    cudaGetSymbolAddress((void**)&p_xh,    g_xh);
    cudaGetSymbolAddress((void**)&p_w1t,   g_w1t);
    cudaGetSymbolAddress((void**)&p_w2t,   g_w2t);
    cudaGetSymbolAddress((void**)&p_h1h,   g_h1h);
    cudaGetSymbolAddress((void**)&p_act1h, g_act1h);
    cudaGetSymbolAddress((void**)&p_h2h,   g_h2h);
    cudaGetSymbolAddress((void**)&p_s1s,   g_s1s);
    cudaGetSymbolAddress((void**)&p_s1d,   g_s1d);
    cudaGetSymbolAddress((void**)&p_s2s,   g_s2s);
    cudaGetSymbolAddress((void**)&p_s2d,   g_s2d);
    cudaGetSymbolAddress((void**)&p_deg,   g_deg);

    // converts (independent of CSR)
    k_cvt_x<<<(N_NODES * F_IN / 4 + 255) / 256, 256>>>(x);
    k_tr_cvt<<<dim3(HC1 / 32, F_IN / 32), dim3(32, 8)>>>(W1, p_w1t, F_IN, HC1);
    k_tr_cvt<<<dim3(C2 / 32, HC1 / 32), dim3(32, 8)>>>(W2, p_w2t, HC1, C2);

    // CSR build
    cudaMemsetAsync(p_deg, 0, N_NODES * sizeof(int));
    k_count<<<(tot + 255) / 256, 256>>>(ei, E);
    k_scan<<<1, 1024>>>();
    k_scatter<<<(tot + 255) / 256, 256>>>(ei, E);

    // Layer 1: fp16 MMA GEMM + fused score1 -> fp16 h1, s1s/s1d
    k_hgemm<128, 64><<<dim3(HC1 / 128, (N_NODES + 127) / 128), 256>>>(
        N_NODES, HC1, F_IN, p_xh, p_w1t, p_h1h,
        p_s1s, p_s1d, a_src1, a_dst1, H1);
    k_agg1<<<N_NODES, 128>>>(b1);

    // Layer 2: fp16 MMA GEMM + fused score2 -> fp16 h2, s2s/s2d
    k_hgemm<64, 32><<<dim3(C2 / 128, (N_NODES + 63) / 64), 256>>>(
        N_NODES, C2, HC1, p_act1h, p_w2t, p_h2h,
        p_s2s, p_s2d, a_src2, a_dst2, 1);
    k_agg2<<<N_NODES, 128>>>(b2, out);
}